// round 5
// baseline (speedup 1.0000x reference)
#include <cuda_runtime.h>
#include <math.h>

// Problem constants
#define B_   1024
#define T_   50
#define IN_  784
#define NSLOT 128
#define D_   40
#define H_   200
#define R_   4
#define C_   5
#define G4H  800          // 4*H
#define KRH  360          // R*D + H
#define BT   (B_*T_)      // 51200

// ---------------- device scratch (static; no allocations) ----------------
__device__ float g_Xpre[BT * G4H];          // precomputed images@Wx + b + offset row
__device__ float g_Wrh[KRH * G4H];          // [Wx rows 789..948 ; Wh] combined
__device__ float g_rh[B_ * KRH];            // state [r(160), h(200)]
__device__ float g_gates[B_ * G4H];
__device__ float g_M[B_ * NSLOT * D_];      // memory
__device__ float g_c[B_ * H_];
__device__ float g_wu[B_ * NSLOT];
__device__ float g_wr[B_ * R_ * NSLOT];
__device__ float g_rowloss[BT];
__device__ float g_rowcorr[BT];

// ---------------- TF32 rounding (matches XLA/cuBLAS f32 dot semantics) ----------------
__device__ __forceinline__ float tf32r(float x) {
    float y;
    asm("cvt.rna.tf32.f32 %0, %1;" : "=f"(y) : "f"(x));
    return y;
}

// ---------------- fast-math-immune precise transcendentals ----------------
__device__ __forceinline__ float exp_acc(float x) {
    x = fminf(fmaxf(x, -87.0f), 88.0f);
    float n = rintf(x * 1.44269504088896341f);
    float r = fmaf(n, -0.693359375f, x);
    r = fmaf(n, 2.12194440e-4f, r);
    float z = r * r;
    float p = 1.9875691500e-4f;
    p = fmaf(p, r, 1.3981999507e-3f);
    p = fmaf(p, r, 8.3334519073e-3f);
    p = fmaf(p, r, 4.1665795894e-2f);
    p = fmaf(p, r, 1.6666665459e-1f);
    p = fmaf(p, r, 5.0000001201e-1f);
    float res = fmaf(p, z, r) + 1.0f;
    int i = (int)n;
    float scale = __int_as_float((i + 127) << 23);
    return res * scale;
}

__device__ __forceinline__ float expm1_small(float y) {
    float p = 2.7557319e-7f;
    p = fmaf(p, y, 2.4801587e-5f);
    p = fmaf(p, y, 1.9841270e-4f);
    p = fmaf(p, y, 1.3888889e-3f);
    p = fmaf(p, y, 8.3333333e-3f);
    p = fmaf(p, y, 4.1666667e-2f);
    p = fmaf(p, y, 1.6666667e-1f);
    p = fmaf(p, y, 0.5f);
    p = fmaf(p, y, 1.0f);
    return y * p;
}

__device__ __forceinline__ float tanh_acc(float x) {
    float a = fabsf(x);
    float t;
    if (a < 0.51f) {
        float em1 = expm1_small(2.0f * a);
        t = __fdiv_rn(em1, em1 + 2.0f);
    } else if (a < 9.1f) {
        float e = exp_acc(2.0f * a);
        t = 1.0f - __fdiv_rn(2.0f, e + 1.0f);
    } else {
        t = 1.0f;
    }
    return copysignf(t, x);
}

__device__ __forceinline__ float sigm(float x) {
    float e = exp_acc(-x);
    return __fdiv_rn(1.0f, 1.0f + e);
}

// ---------------- init ----------------
__global__ void init_kernel(const float* __restrict__ Wx, const float* __restrict__ Wh) {
    int idx = blockIdx.x * blockDim.x + threadIdx.x;
    int stride = gridDim.x * blockDim.x;
    for (int i = idx; i < B_ * NSLOT * D_; i += stride) g_M[i] = 1e-6f;
    for (int i = idx; i < B_ * KRH; i += stride) { int j = i % KRH; g_rh[i] = (j < R_*D_) ? 1e-6f : 0.f; }
    for (int i = idx; i < B_ * H_;  i += stride) g_c[i] = 0.f;
    for (int i = idx; i < B_ * NSLOT; i += stride) g_wu[i] = ((i & (NSLOT-1)) == 0) ? 1.f : 0.f;
    for (int i = idx; i < B_ * R_ * NSLOT; i += stride) g_wr[i] = ((i & (NSLOT-1)) == 0) ? 1.f : 0.f;
    for (int i = idx; i < KRH * G4H; i += stride) {
        int row = i / G4H, col = i % G4H;
        g_Wrh[i] = (row < R_*D_) ? Wx[(IN_ + C_ + row) * G4H + col]
                                 : Wh[(row - R_*D_) * G4H + col];
    }
}

// ---------------- tiled GEMM (TF32-rounded operands, fp32 accumulate) ----------------
// EPI 0: Xpre precompute: += b_lstm[col](fp32) + (t>0 ? tf32(Wx[(IN+lab[m-1])*800+col]) : 0)
// EPI 1: gates:           += Xpre[(m*T + t)*800 + col]
#define BM 64
#define BN 64
#define KT 8

template <int EPI>
__global__ __launch_bounds__(256) void gemm_kernel(
    const float* __restrict__ A, const float* __restrict__ W, float* __restrict__ Cout,
    int Mrows, int K, int Ncols,
    const float* __restrict__ e0, const float* __restrict__ e1,
    const int* __restrict__ labs, int t)
{
    __shared__ float As[KT][BM];
    __shared__ float Bs[KT][BN];
    int tid = threadIdx.x;
    int tx = tid & 15, ty = tid >> 4;
    int m0 = blockIdx.y * BM;
    int n0 = blockIdx.x * BN;
    float acc[4][4];
#pragma unroll
    for (int i = 0; i < 4; i++)
#pragma unroll
        for (int j = 0; j < 4; j++) acc[i][j] = 0.f;

    for (int k0 = 0; k0 < K; k0 += KT) {
#pragma unroll
        for (int e = tid; e < BM * KT; e += 256) {
            int m = e >> 3, k = e & 7;
            As[k][m] = tf32r(A[(size_t)(m0 + m) * K + k0 + k]);
        }
#pragma unroll
        for (int e = tid; e < KT * BN; e += 256) {
            int k = e >> 6, n = e & 63;
            float v = 0.f;
            if (n0 + n < Ncols) v = tf32r(W[(size_t)(k0 + k) * Ncols + n0 + n]);
            Bs[k][n] = v;
        }
        __syncthreads();
#pragma unroll
        for (int k = 0; k < KT; k++) {
            float a[4], bb[4];
#pragma unroll
            for (int i = 0; i < 4; i++) a[i] = As[k][ty * 4 + i];
#pragma unroll
            for (int j = 0; j < 4; j++) bb[j] = Bs[k][tx * 4 + j];
#pragma unroll
            for (int i = 0; i < 4; i++)
#pragma unroll
                for (int j = 0; j < 4; j++) acc[i][j] = fmaf(a[i], bb[j], acc[i][j]);
        }
        __syncthreads();
    }
#pragma unroll
    for (int i = 0; i < 4; i++) {
        int m = m0 + ty * 4 + i;
#pragma unroll
        for (int j = 0; j < 4; j++) {
            int n = n0 + tx * 4 + j;
            if (n < Ncols) {
                float v = acc[i][j];
                if (EPI == 0) {
                    v += e0[n];
                    int tt = m % T_;
                    if (tt > 0) v += tf32r(e1[(size_t)(IN_ + labs[m - 1]) * G4H + n]);
                } else {
                    v += e0[(size_t)(m * T_ + t) * G4H + n];
                }
                Cout[(size_t)m * Ncols + n] = v;
            }
        }
    }
}

// ---------------- fused per-step kernel: one block per batch element ----------------
__global__ __launch_bounds__(256) void step_kernel(
    const float* __restrict__ Wp, const float* __restrict__ bp,
    const float* __restrict__ Wc, const float* __restrict__ bc,
    const int* __restrict__ labels, float* __restrict__ out, int t)
{
    int b = blockIdx.x;
    int tid = threadIdx.x;

    __shared__ float sM[NSLOT * D_];     // 20KB
    __shared__ float sh[H_];
    __shared__ float sk[R_ * D_];        // raw keys (tanh output)
    __shared__ float skn[R_ * D_];       // normalized keys, tf32-rounded
    __shared__ float ssig[R_];
    __shared__ float sMnorm[NSLOT];
    __shared__ float swr[R_ * NSLOT];
    __shared__ float sww[R_ * NSLOT];
    __shared__ float swu[NSLOT];
    __shared__ int   s_lu[R_];
    __shared__ float s_rnew[R_ * D_];
    __shared__ float slog[C_];

    const float* gates = g_gates + (size_t)b * G4H;

    for (int i = tid; i < NSLOT * D_; i += 256) sM[i] = g_M[(size_t)b * NSLOT * D_ + i];
    if (tid < NSLOT) swu[tid] = g_wu[b * NSLOT + tid];
    if (tid < H_) {
        float ig = gates[tid], fg = gates[H_ + tid], gg = gates[2*H_ + tid], og = gates[3*H_ + tid];
        float c_old = g_c[b * H_ + tid];
        float c_new = sigm(fg) * c_old + sigm(ig) * tanh_acc(gg);
        float h_new = sigm(og) * tanh_acc(c_new);
        g_c[b * H_ + tid] = c_new;
        sh[tid] = h_new;
    }
    __syncthreads();

    // p = h @ Wp + bp (TF32 dot, fp32 bias) ; keys + sigma
    if (tid < R_ * (D_ + 1)) {
        float acc = 0.f;
        for (int j = 0; j < H_; j++)
            acc = fmaf(tf32r(sh[j]), tf32r(Wp[j * (R_ * (D_ + 1)) + tid]), acc);
        acc += bp[tid];
        int r = tid / (D_ + 1), w = tid % (D_ + 1);
        if (w < D_) sk[r * D_ + w] = tanh_acc(acc);
        else        ssig[r] = sigm(acc);
    }
    __syncthreads();

    // norms (fp32), normalized operands tf32-rounded (matching ref: normalize then dot)
    if (tid < NSLOT) {
        float s = 0.f;
        for (int d = 0; d < D_; d++) { float v = sM[tid * D_ + d]; s = fmaf(v, v, s); }
        sMnorm[tid] = __fsqrt_rn(s) + 1e-8f;
    } else if (tid < NSLOT + R_) {
        int r = tid - NSLOT;
        float s = 0.f;
        for (int d = 0; d < D_; d++) { float v = sk[r * D_ + d]; s = fmaf(v, v, s); }
        float kn = __fsqrt_rn(s) + 1e-8f;
        for (int d = 0; d < D_; d++) skn[r * D_ + d] = tf32r(__fdiv_rn(sk[r * D_ + d], kn));
    } else if (tid == NSLOT + R_) {
        // least-used selection: R sequential strict-< minima (lowest index on ties)
        int chosen[R_];
        for (int s = 0; s < R_; s++) {
            float best = 3.0e38f; int bi = 0;
            for (int n = 0; n < NSLOT; n++) {
                bool skip = false;
                for (int q = 0; q < s; q++) if (chosen[q] == n) skip = true;
                if (skip) continue;
                if (swu[n] < best) { best = swu[n]; bi = n; }
            }
            chosen[s] = bi; s_lu[s] = bi;
        }
    }
    __syncthreads();

    // cosine-similarity logits: dot(tf32(kn), tf32(Mn)), fp32 accumulate
    if (tid < NSLOT) {
        int n = tid;
        float invm = sMnorm[n];
        float a0 = 0.f, a1 = 0.f, a2 = 0.f, a3 = 0.f;
        for (int d = 0; d < D_; d++) {
            float mn = tf32r(__fdiv_rn(sM[n * D_ + d], invm));
            a0 = fmaf(mn, skn[d], a0);
            a1 = fmaf(mn, skn[D_ + d], a1);
            a2 = fmaf(mn, skn[2*D_ + d], a2);
            a3 = fmaf(mn, skn[3*D_ + d], a3);
        }
        swr[n]           = a0;
        swr[NSLOT + n]   = a1;
        swr[2*NSLOT + n] = a2;
        swr[3*NSLOT + n] = a3;
    }
    __syncthreads();

    // softmax over N per head: warp r handles row r
    if (tid < R_ * 32) {
        int r = tid >> 5, lane = tid & 31;
        float v0 = swr[r*NSLOT + lane],      v1 = swr[r*NSLOT + lane + 32];
        float v2 = swr[r*NSLOT + lane + 64], v3 = swr[r*NSLOT + lane + 96];
        float mx = fmaxf(fmaxf(v0, v1), fmaxf(v2, v3));
        for (int o = 16; o > 0; o >>= 1) mx = fmaxf(mx, __shfl_xor_sync(0xffffffffu, mx, o));
        float e0 = exp_acc(v0 - mx), e1 = exp_acc(v1 - mx), e2 = exp_acc(v2 - mx), e3 = exp_acc(v3 - mx);
        float s = e0 + e1 + e2 + e3;
        for (int o = 16; o > 0; o >>= 1) s += __shfl_xor_sync(0xffffffffu, s, o);
        swr[r*NSLOT + lane]      = __fdiv_rn(e0, s);
        swr[r*NSLOT + lane + 32] = __fdiv_rn(e1, s);
        swr[r*NSLOT + lane + 64] = __fdiv_rn(e2, s);
        swr[r*NSLOT + lane + 96] = __fdiv_rn(e3, s);
    }
    __syncthreads();

    // write weights (elementwise, fp32)
    for (int idx = tid; idx < R_ * NSLOT; idx += 256) {
        int r = idx >> 7, n = idx & (NSLOT - 1);
        float wlu = (n == s_lu[0] || n == s_lu[1] || n == s_lu[2] || n == s_lu[3]) ? 1.f : 0.f;
        float sg = ssig[r];
        sww[idx] = sg * g_wr[(size_t)b * R_ * NSLOT + idx] + (1.f - sg) * wlu;
    }
    __syncthreads();

    // usage update + persist read weights + memory update (write einsum in TF32)
    if (tid < NSLOT) {
        float v = 0.95f * swu[tid];
        for (int r = 0; r < R_; r++) v += swr[r*NSLOT + tid] + sww[r*NSLOT + tid];
        g_wu[b * NSLOT + tid] = v;
    }
    for (int idx = tid; idx < R_ * NSLOT; idx += 256) g_wr[(size_t)b * R_ * NSLOT + idx] = swr[idx];
    for (int idx = tid; idx < NSLOT * D_; idx += 256) {
        int n = idx / D_, d = idx - n * D_;
        float base = (n == s_lu[R_ - 1]) ? 0.f : sM[idx];
        float add = 0.f;
        add = fmaf(tf32r(sww[n]),           tf32r(sk[d]),        add);
        add = fmaf(tf32r(sww[NSLOT + n]),   tf32r(sk[D_ + d]),   add);
        add = fmaf(tf32r(sww[2*NSLOT + n]), tf32r(sk[2*D_ + d]), add);
        add = fmaf(tf32r(sww[3*NSLOT + n]), tf32r(sk[3*D_ + d]), add);
        sM[idx] = base + add;
    }
    __syncthreads();

    for (int idx = tid; idx < NSLOT * D_; idx += 256) g_M[(size_t)b * NSLOT * D_ + idx] = sM[idx];
    // r_new = w_r @ M_new   (threads 0..159)
    if (tid < R_ * D_) {
        int r = tid / D_, d = tid - r * D_;
        float acc = 0.f;
        for (int n = 0; n < NSLOT; n++)
            acc = fmaf(tf32r(swr[r*NSLOT + n]), tf32r(sM[n * D_ + d]), acc);
        s_rnew[tid] = acc;
        g_rh[(size_t)b * KRH + tid] = acc;              // r part of state
    }
    // h part of state: FIX — own guard (tid<200<256); old code used tid in [160,360) which
    // exceeded blockDim=256, leaving h[96..199] frozen at 0 for the whole sequence.
    if (tid < H_) {
        g_rh[(size_t)b * KRH + R_ * D_ + tid] = sh[tid];
    }
    __syncthreads();

    // classifier logits (TF32 dot + fp32 bias)
    if (tid < C_) {
        float acc = 0.f;
        for (int j = 0; j < H_; j++)
            acc = fmaf(tf32r(sh[j]), tf32r(Wc[j * C_ + tid]), acc);
        for (int j = 0; j < R_ * D_; j++)
            acc = fmaf(tf32r(s_rnew[j]), tf32r(Wc[(H_ + j) * C_ + tid]), acc);
        slog[tid] = acc + bc[tid];
    }
    __syncthreads();

    if (tid == 0) {
        int m = b * T_ + t;
        float mx = slog[0]; int am = 0;
        for (int c = 1; c < C_; c++) if (slog[c] > mx) { mx = slog[c]; am = c; }
        float e[C_], s = 0.f;
        for (int c = 0; c < C_; c++) { e[c] = exp_acc(slog[c] - mx); s += e[c]; }
        float pr[C_];
        for (int c = 0; c < C_; c++) { pr[c] = __fdiv_rn(e[c], s); out[m * C_ + c] = pr[c]; }
        // loss row: logsumexp(probs) - probs[label]
        float mp = pr[0];
        for (int c = 1; c < C_; c++) mp = fmaxf(mp, pr[c]);
        float se = 0.f;
        for (int c = 0; c < C_; c++) se += exp_acc(pr[c] - mp);
        int lab = labels[m];
        g_rowloss[m] = (float)(log((double)se)) + mp - pr[lab];
        g_rowcorr[m] = (am == lab) ? 1.f : 0.f;
    }
}

// ---------------- deterministic final reduction ----------------
__global__ __launch_bounds__(256) void finalize_kernel(float* __restrict__ out) {
    __shared__ float sl[256], sa[256];
    int tid = threadIdx.x;
    float l = 0.f, a = 0.f;
    for (int i = tid; i < BT; i += 256) { l += g_rowloss[i]; a += g_rowcorr[i]; }
    sl[tid] = l; sa[tid] = a;
    __syncthreads();
    for (int s = 128; s > 0; s >>= 1) {
        if (tid < s) { sl[tid] += sl[tid + s]; sa[tid] += sa[tid + s]; }
        __syncthreads();
    }
    if (tid == 0) {
        out[BT * C_]     = __fdiv_rn(sl[0], (float)BT);
        out[BT * C_ + 1] = __fdiv_rn(sa[0], (float)BT);
    }
}

// ---------------- launch ----------------
extern "C" void kernel_launch(void* const* d_in, const int* in_sizes, int n_in,
                              void* d_out, int out_size) {
    const float* images = (const float*)d_in[0];
    const int*   labels = (const int*)d_in[1];
    const float* Wx     = (const float*)d_in[2];
    const float* Wh     = (const float*)d_in[3];
    const float* b_lstm = (const float*)d_in[4];
    const float* Wp     = (const float*)d_in[5];
    const float* bp     = (const float*)d_in[6];
    const float* Wc     = (const float*)d_in[7];
    const float* bc     = (const float*)d_in[8];
    float* out = (float*)d_out;

    float *pXpre, *pWrh, *pRh, *pGates;
    cudaGetSymbolAddress((void**)&pXpre,  g_Xpre);
    cudaGetSymbolAddress((void**)&pWrh,   g_Wrh);
    cudaGetSymbolAddress((void**)&pRh,    g_rh);
    cudaGetSymbolAddress((void**)&pGates, g_gates);

    init_kernel<<<1024, 256>>>(Wx, Wh);

    // hoisted time-invariant GEMM: Xpre = images @ Wx[:784] + b_lstm + offset-label row
    {
        dim3 grid((G4H + BN - 1) / BN, BT / BM);
        gemm_kernel<0><<<grid, 256>>>(images, Wx, pXpre, BT, IN_, G4H, b_lstm, Wx, labels, 0);
    }

    for (int t = 0; t < T_; t++) {
        dim3 gB((G4H + BN - 1) / BN, B_ / BM);
        gemm_kernel<1><<<gB, 256>>>(pRh, pWrh, pGates, B_, KRH, G4H, pXpre, nullptr, nullptr, t);
        step_kernel<<<B_, 256>>>(Wp, bp, Wc, bc, labels, out, t);
    }

    finalize_kernel<<<1, 256>>>(out);
}

// round 6
// speedup vs baseline: 1.7588x; 1.7588x over previous
#include <cuda_runtime.h>
#include <math.h>
#include <stdint.h>

#define B_   1024
#define T_   50
#define IN_  784
#define NSLOT 128
#define D_   40
#define H_   200
#define R_   4
#define C_   5
#define G4H  800
#define KRH  360
#define BT   (B_*T_)

// ---------------- device scratch ----------------
__device__ float g_Xpre[BT * G4H];
__device__ float g_Wrh[KRH * G4H];
__device__ float g_rh[B_ * KRH];
__device__ float g_gates[B_ * G4H];
__device__ float g_M[B_ * NSLOT * D_];
__device__ float g_c[B_ * H_];
__device__ float g_wu[B_ * NSLOT];
__device__ float g_wr[B_ * R_ * NSLOT];
__device__ float g_rowloss[BT];
__device__ float g_rowcorr[BT];

__device__ __forceinline__ float tf32r(float x) {
    float y;
    asm("cvt.rna.tf32.f32 %0, %1;" : "=f"(y) : "f"(x));
    return y;
}

// ---------------- precise transcendentals (fast-math immune) ----------------
__device__ __forceinline__ float exp_acc(float x) {
    x = fminf(fmaxf(x, -87.0f), 88.0f);
    float n = rintf(x * 1.44269504088896341f);
    float r = fmaf(n, -0.693359375f, x);
    r = fmaf(n, 2.12194440e-4f, r);
    float z = r * r;
    float p = 1.9875691500e-4f;
    p = fmaf(p, r, 1.3981999507e-3f);
    p = fmaf(p, r, 8.3334519073e-3f);
    p = fmaf(p, r, 4.1665795894e-2f);
    p = fmaf(p, r, 1.6666665459e-1f);
    p = fmaf(p, r, 5.0000001201e-1f);
    float res = fmaf(p, z, r) + 1.0f;
    int i = (int)n;
    float scale = __int_as_float((i + 127) << 23);
    return res * scale;
}
__device__ __forceinline__ float expm1_small(float y) {
    float p = 2.7557319e-7f;
    p = fmaf(p, y, 2.4801587e-5f);
    p = fmaf(p, y, 1.9841270e-4f);
    p = fmaf(p, y, 1.3888889e-3f);
    p = fmaf(p, y, 8.3333333e-3f);
    p = fmaf(p, y, 4.1666667e-2f);
    p = fmaf(p, y, 1.6666667e-1f);
    p = fmaf(p, y, 0.5f);
    p = fmaf(p, y, 1.0f);
    return y * p;
}
__device__ __forceinline__ float tanh_acc(float x) {
    float a = fabsf(x);
    float t;
    if (a < 0.51f) {
        float em1 = expm1_small(2.0f * a);
        t = __fdiv_rn(em1, em1 + 2.0f);
    } else if (a < 9.1f) {
        float e = exp_acc(2.0f * a);
        t = 1.0f - __fdiv_rn(2.0f, e + 1.0f);
    } else {
        t = 1.0f;
    }
    return copysignf(t, x);
}
__device__ __forceinline__ float sigm(float x) {
    float e = exp_acc(-x);
    return __fdiv_rn(1.0f, 1.0f + e);
}

// ---------------- init ----------------
__global__ void init_kernel(const float* __restrict__ Wx, const float* __restrict__ Wh) {
    int idx = blockIdx.x * blockDim.x + threadIdx.x;
    int stride = gridDim.x * blockDim.x;
    for (int i = idx; i < B_ * NSLOT * D_; i += stride) g_M[i] = 1e-6f;
    for (int i = idx; i < B_ * KRH; i += stride) { int j = i % KRH; g_rh[i] = (j < R_*D_) ? 1e-6f : 0.f; }
    for (int i = idx; i < B_ * H_;  i += stride) g_c[i] = 0.f;
    for (int i = idx; i < B_ * NSLOT; i += stride) g_wu[i] = ((i & (NSLOT-1)) == 0) ? 1.f : 0.f;
    for (int i = idx; i < B_ * R_ * NSLOT; i += stride) g_wr[i] = ((i & (NSLOT-1)) == 0) ? 1.f : 0.f;
    for (int i = idx; i < KRH * G4H; i += stride) {
        int row = i / G4H, col = i % G4H;
        g_Wrh[i] = (row < R_*D_) ? Wx[(IN_ + C_ + row) * G4H + col]
                                 : Wh[(row - R_*D_) * G4H + col];
    }
}

// ---------------- tf32 tensor-core GEMM:  C[M,800] = A[M,K] @ W[K,800] + EPI ----------------
// EPI 0: += b_lstm[col] + (row%T>0 ? tf32(Wx[(IN+lab[row-1])*800+col]) : 0)
// EPI 1: += Xpre[(row*T + t)*800 + col]
__device__ __forceinline__ void mma_tf32(float& c0, float& c1, float& c2, float& c3,
                                         uint32_t a0, uint32_t a1, uint32_t a2, uint32_t a3,
                                         uint32_t b0, uint32_t b1) {
    asm volatile(
        "mma.sync.aligned.m16n8k8.row.col.f32.tf32.tf32.f32 "
        "{%0,%1,%2,%3}, {%4,%5,%6,%7}, {%8,%9}, {%0,%1,%2,%3};\n"
        : "+f"(c0), "+f"(c1), "+f"(c2), "+f"(c3)
        : "r"(a0), "r"(a1), "r"(a2), "r"(a3), "r"(b0), "r"(b1));
}

template <int BMT, int EPI>
__global__ __launch_bounds__(256) void mma_gemm(
    const float* __restrict__ A, const float* __restrict__ W, float* __restrict__ Cout,
    int K, int lda,
    const float* __restrict__ e0, const float* __restrict__ e1,
    const int* __restrict__ labs, int t)
{
    constexpr int WARPS_M = BMT / 32;         // 4 or 2
    constexpr int WARPS_N = 8 / WARPS_M;      // 2 or 4
    constexpr int WN = 64 / WARPS_N;          // 32 or 16
    constexpr int NT = WN / 8;                // 4 or 2
    constexpr int MT = 2;

    __shared__ float As[BMT][36];             // 32 K-cols + pad4 (stride%32==4 -> conflict-free frags)
    __shared__ float Bs[32][68];

    int tid = threadIdx.x;
    int lane = tid & 31, warp = tid >> 5;
    int wm = warp / WARPS_N, wn = warp % WARPS_N;
    int m0 = blockIdx.y * BMT;
    int n0 = blockIdx.x * 64;
    const int lr = lane >> 2, lc = lane & 3;

    float c[MT][NT][4];
#pragma unroll
    for (int i = 0; i < MT; i++)
#pragma unroll
        for (int j = 0; j < NT; j++)
#pragma unroll
            for (int q = 0; q < 4; q++) c[i][j][q] = 0.f;

    int ar = tid >> 3;            // 0..31
    int ac4 = (tid & 7) * 4;      // k offset (float4)
    int br = tid >> 4;            // 0..15
    int bc4 = (tid & 15) * 4;     // n offset (float4)

    for (int k0 = 0; k0 < K; k0 += 32) {
        // load A tile (BMT x 32)
#pragma unroll
        for (int p = 0; p < BMT / 32; p++) {
            int row = ar + p * 32;
            const float* src = A + (size_t)(m0 + row) * lda + k0 + ac4;
            if (k0 + ac4 + 3 < K) {
                float4 v = *reinterpret_cast<const float4*>(src);
                As[row][ac4 + 0] = tf32r(v.x);
                As[row][ac4 + 1] = tf32r(v.y);
                As[row][ac4 + 2] = tf32r(v.z);
                As[row][ac4 + 3] = tf32r(v.w);
            } else {
#pragma unroll
                for (int i = 0; i < 4; i++) {
                    int k = k0 + ac4 + i;
                    As[row][ac4 + i] = (k < K) ? tf32r(src[i]) : 0.f;
                }
            }
        }
        // load B tile (32 x 64) from W[K][800]
#pragma unroll
        for (int p = 0; p < 2; p++) {
            int krow = k0 + br + p * 16;
            bool ok = (krow < K) && (n0 + bc4 + 3 < G4H);
            float4 v = make_float4(0.f, 0.f, 0.f, 0.f);
            if (ok) v = *reinterpret_cast<const float4*>(W + (size_t)krow * G4H + n0 + bc4);
            Bs[br + p * 16][bc4 + 0] = tf32r(v.x);
            Bs[br + p * 16][bc4 + 1] = tf32r(v.y);
            Bs[br + p * 16][bc4 + 2] = tf32r(v.z);
            Bs[br + p * 16][bc4 + 3] = tf32r(v.w);
        }
        __syncthreads();

#pragma unroll
        for (int k8 = 0; k8 < 4; k8++) {
            int kk = k8 * 8;
            uint32_t a[MT][4];
#pragma unroll
            for (int mt = 0; mt < MT; mt++) {
                int arow = wm * 32 + mt * 16 + lr;
                a[mt][0] = __float_as_uint(As[arow][kk + lc]);
                a[mt][1] = __float_as_uint(As[arow + 8][kk + lc]);
                a[mt][2] = __float_as_uint(As[arow][kk + lc + 4]);
                a[mt][3] = __float_as_uint(As[arow + 8][kk + lc + 4]);
            }
#pragma unroll
            for (int nt = 0; nt < NT; nt++) {
                int bcol = wn * WN + nt * 8 + lr;
                uint32_t b0 = __float_as_uint(Bs[kk + lc][bcol]);
                uint32_t b1 = __float_as_uint(Bs[kk + lc + 4][bcol]);
#pragma unroll
                for (int mt = 0; mt < MT; mt++)
                    mma_tf32(c[mt][nt][0], c[mt][nt][1], c[mt][nt][2], c[mt][nt][3],
                             a[mt][0], a[mt][1], a[mt][2], a[mt][3], b0, b1);
            }
        }
        __syncthreads();
    }

    // epilogue + store
#pragma unroll
    for (int mt = 0; mt < MT; mt++) {
        int row0 = m0 + wm * 32 + mt * 16 + lr;
#pragma unroll
        for (int rr = 0; rr < 2; rr++) {
            int row = row0 + rr * 8;
            int tt = 0, lab = 0;
            if (EPI == 0) {
                tt = row % T_;
                if (tt > 0) lab = labs[row - 1];
            }
#pragma unroll
            for (int nt = 0; nt < NT; nt++) {
                int col = n0 + wn * WN + nt * 8 + 2 * lc;
#pragma unroll
                for (int cc = 0; cc < 2; cc++) {
                    int cg = col + cc;
                    if (cg < G4H) {
                        float v = c[mt][nt][rr * 2 + cc];
                        if (EPI == 0) {
                            v += e0[cg];
                            if (tt > 0) v += tf32r(e1[(size_t)(IN_ + lab) * G4H + cg]);
                        } else {
                            v += e0[(size_t)(row * T_ + t) * G4H + cg];
                        }
                        Cout[(size_t)row * G4H + cg] = v;
                    }
                }
            }
        }
    }
}

// ---------------- fused per-step kernel: one block per batch element ----------------
__global__ __launch_bounds__(256) void step_kernel(
    const float* __restrict__ Wp, const float* __restrict__ bp,
    const float* __restrict__ Wc, const float* __restrict__ bc,
    const int* __restrict__ labels, float* __restrict__ out, int t)
{
    int b = blockIdx.x;
    int tid = threadIdx.x;
    int lane = tid & 31, warp = tid >> 5;

    __shared__ float sM[NSLOT * D_];     // 20KB
    __shared__ float sh[H_];
    __shared__ float sk[R_ * D_];
    __shared__ float skn[R_ * D_];
    __shared__ float ssig[R_];
    __shared__ float sMnorm[NSLOT];
    __shared__ float swr[R_ * NSLOT];
    __shared__ float sww[R_ * NSLOT];
    __shared__ float swu[NSLOT];
    __shared__ int   s_lu[R_];
    __shared__ float s_rnew[R_ * D_];
    __shared__ float slog[C_];

    const float* gates = g_gates + (size_t)b * G4H;

    // P1: load memory/usage + LSTM pointwise
    for (int i = tid; i < NSLOT * D_; i += 256) sM[i] = g_M[(size_t)b * NSLOT * D_ + i];
    if (tid < NSLOT) swu[tid] = g_wu[b * NSLOT + tid];
    if (tid < H_) {
        float ig = gates[tid], fg = gates[H_ + tid], gg = gates[2*H_ + tid], og = gates[3*H_ + tid];
        float c_old = g_c[b * H_ + tid];
        float c_new = sigm(fg) * c_old + sigm(ig) * tanh_acc(gg);
        float h_new = sigm(og) * tanh_acc(c_new);
        g_c[b * H_ + tid] = c_new;
        sh[tid] = h_new;
    }
    __syncthreads();

    // P2: h@Wp (tid<164, 4 accumulators) || M row norms (tid in [192,256))
    if (tid < R_ * (D_ + 1)) {
        const float* wp = Wp + tid;
        float a0 = 0.f, a1 = 0.f, a2 = 0.f, a3 = 0.f;
#pragma unroll 4
        for (int j = 0; j < H_; j += 4) {
            a0 = fmaf(tf32r(sh[j]),     tf32r(wp[(j)     * 164]), a0);
            a1 = fmaf(tf32r(sh[j + 1]), tf32r(wp[(j + 1) * 164]), a1);
            a2 = fmaf(tf32r(sh[j + 2]), tf32r(wp[(j + 2) * 164]), a2);
            a3 = fmaf(tf32r(sh[j + 3]), tf32r(wp[(j + 3) * 164]), a3);
        }
        float acc = ((a0 + a1) + (a2 + a3)) + bp[tid];
        int r = tid / (D_ + 1), w = tid % (D_ + 1);
        if (w < D_) sk[r * D_ + w] = tanh_acc(acc);
        else        ssig[r] = sigm(acc);
    } else if (tid >= 192) {
#pragma unroll
        for (int q = 0; q < 2; q++) {
            int n = (tid - 192) + q * 64;
            float s = 0.f;
            for (int d = 0; d < D_; d++) { float v = sM[n * D_ + d]; s = fmaf(v, v, s); }
            sMnorm[n] = __fsqrt_rn(s) + 1e-8f;
        }
    }
    __syncthreads();

    // P3: LU selection (warp 0, lexicographic min-reduce) || key norms + normalized keys (tid 32..35)
    if (warp == 0) {
        float v0 = swu[lane], v1 = swu[lane + 32], v2 = swu[lane + 64], v3 = swu[lane + 96];
        int i0 = lane, i1 = lane + 32, i2 = lane + 64, i3 = lane + 96;
#pragma unroll
        for (int s = 0; s < R_; s++) {
            float bv = v0; int bi = i0;
            if (v1 < bv || (v1 == bv && i1 < bi)) { bv = v1; bi = i1; }
            if (v2 < bv || (v2 == bv && i2 < bi)) { bv = v2; bi = i2; }
            if (v3 < bv || (v3 == bv && i3 < bi)) { bv = v3; bi = i3; }
#pragma unroll
            for (int o = 16; o > 0; o >>= 1) {
                float ov = __shfl_xor_sync(0xffffffffu, bv, o);
                int   oi = __shfl_xor_sync(0xffffffffu, bi, o);
                if (ov < bv || (ov == bv && oi < bi)) { bv = ov; bi = oi; }
            }
            if (lane == 0) s_lu[s] = bi;
            if      (bi == i0) v0 = 3.0e38f;
            else if (bi == i1) v1 = 3.0e38f;
            else if (bi == i2) v2 = 3.0e38f;
            else if (bi == i3) v3 = 3.0e38f;
        }
    } else if (tid >= 32 && tid < 36) {
        int r = tid - 32;
        float s = 0.f;
        for (int d = 0; d < D_; d++) { float v = sk[r * D_ + d]; s = fmaf(v, v, s); }
        float kn = __fsqrt_rn(s) + 1e-8f;
        for (int d = 0; d < D_; d++) skn[r * D_ + d] = tf32r(__fdiv_rn(sk[r * D_ + d], kn));
    }
    __syncthreads();

    // P4: cosine logits (tid<128): dot(tf32(Mn), tf32(kn)), fp32 accumulate
    if (tid < NSLOT) {
        int n = tid;
        float rinv = __fdiv_rn(1.0f, sMnorm[n]);
        float a0 = 0.f, a1 = 0.f, a2 = 0.f, a3 = 0.f;
        for (int d = 0; d < D_; d++) {
            float mn = tf32r(sM[n * D_ + d] * rinv);
            a0 = fmaf(mn, skn[d],        a0);
            a1 = fmaf(mn, skn[D_ + d],   a1);
            a2 = fmaf(mn, skn[2*D_ + d], a2);
            a3 = fmaf(mn, skn[3*D_ + d], a3);
        }
        swr[n]           = a0;
        swr[NSLOT + n]   = a1;
        swr[2*NSLOT + n] = a2;
        swr[3*NSLOT + n] = a3;
    }
    __syncthreads();

    // P5: softmax per head (warps 0-3)
    if (tid < R_ * 32) {
        int r = warp;
        float v0 = swr[r*NSLOT + lane],      v1 = swr[r*NSLOT + lane + 32];
        float v2 = swr[r*NSLOT + lane + 64], v3 = swr[r*NSLOT + lane + 96];
        float mx = fmaxf(fmaxf(v0, v1), fmaxf(v2, v3));
        for (int o = 16; o > 0; o >>= 1) mx = fmaxf(mx, __shfl_xor_sync(0xffffffffu, mx, o));
        float e0 = exp_acc(v0 - mx), e1 = exp_acc(v1 - mx), e2 = exp_acc(v2 - mx), e3 = exp_acc(v3 - mx);
        float s = e0 + e1 + e2 + e3;
        for (int o = 16; o > 0; o >>= 1) s += __shfl_xor_sync(0xffffffffu, s, o);
        swr[r*NSLOT + lane]      = __fdiv_rn(e0, s);
        swr[r*NSLOT + lane + 32] = __fdiv_rn(e1, s);
        swr[r*NSLOT + lane + 64] = __fdiv_rn(e2, s);
        swr[r*NSLOT + lane + 96] = __fdiv_rn(e3, s);
    }
    __syncthreads();

    // P6: write weights
    for (int idx = tid; idx < R_ * NSLOT; idx += 256) {
        int r = idx >> 7, n = idx & (NSLOT - 1);
        float wlu = (n == s_lu[0] || n == s_lu[1] || n == s_lu[2] || n == s_lu[3]) ? 1.f : 0.f;
        float sg = ssig[r];
        sww[idx] = sg * g_wr[(size_t)b * R_ * NSLOT + idx] + (1.f - sg) * wlu;
    }
    __syncthreads();

    // P7: usage update + persist read weights + memory update
    if (tid < NSLOT) {
        float v = 0.95f * swu[tid];
        for (int r = 0; r < R_; r++) v += swr[r*NSLOT + tid] + sww[r*NSLOT + tid];
        g_wu[b * NSLOT + tid] = v;
    }
    for (int idx = tid; idx < R_ * NSLOT; idx += 256) g_wr[(size_t)b * R_ * NSLOT + idx] = swr[idx];
    for (int idx = tid; idx < NSLOT * D_; idx += 256) {
        int n = idx / D_, d = idx - n * D_;
        float base = (n == s_lu[R_ - 1]) ? 0.f : sM[idx];
        float add = 0.f;
        add = fmaf(tf32r(sww[n]),           tf32r(sk[d]),        add);
        add = fmaf(tf32r(sww[NSLOT + n]),   tf32r(sk[D_ + d]),   add);
        add = fmaf(tf32r(sww[2*NSLOT + n]), tf32r(sk[2*D_ + d]), add);
        add = fmaf(tf32r(sww[3*NSLOT + n]), tf32r(sk[3*D_ + d]), add);
        sM[idx] = base + add;
    }
    __syncthreads();

    // P8: persist M; read einsum (tid<160, 4 accumulators); persist h state
    for (int idx = tid; idx < NSLOT * D_; idx += 256) g_M[(size_t)b * NSLOT * D_ + idx] = sM[idx];
    if (tid < R_ * D_) {
        int r = tid / D_, d = tid - r * D_;
        const float* wrow = swr + r * NSLOT;
        float a0 = 0.f, a1 = 0.f, a2 = 0.f, a3 = 0.f;
        for (int n = 0; n < NSLOT; n += 4) {
            a0 = fmaf(tf32r(wrow[n]),     tf32r(sM[(n)     * D_ + d]), a0);
            a1 = fmaf(tf32r(wrow[n + 1]), tf32r(sM[(n + 1) * D_ + d]), a1);
            a2 = fmaf(tf32r(wrow[n + 2]), tf32r(sM[(n + 2) * D_ + d]), a2);
            a3 = fmaf(tf32r(wrow[n + 3]), tf32r(sM[(n + 3) * D_ + d]), a3);
        }
        float acc = (a0 + a1) + (a2 + a3);
        s_rnew[tid] = acc;
        g_rh[(size_t)b * KRH + tid] = acc;
    }
    if (tid < H_) {
        g_rh[(size_t)b * KRH + R_ * D_ + tid] = sh[tid];
    }
    __syncthreads();

    // P9: classifier — warp c computes logit c via lane-parallel reduce
    if (warp < C_) {
        int cI = warp;
        float acc = 0.f;
        for (int j = lane; j < KRH; j += 32) {
            float v = (j < H_) ? sh[j] : s_rnew[j - H_];
            acc = fmaf(tf32r(v), tf32r(Wc[j * C_ + cI]), acc);
        }
#pragma unroll
        for (int o = 16; o > 0; o >>= 1) acc += __shfl_xor_sync(0xffffffffu, acc, o);
        if (lane == 0) slog[cI] = acc + bc[cI];
    }
    __syncthreads();

    // P10: probs + loss/acc rows
    if (tid == 0) {
        int m = b * T_ + t;
        float mx = slog[0]; int am = 0;
        for (int c = 1; c < C_; c++) if (slog[c] > mx) { mx = slog[c]; am = c; }
        float e[C_], s = 0.f;
        for (int c = 0; c < C_; c++) { e[c] = exp_acc(slog[c] - mx); s += e[c]; }
        float pr[C_];
        for (int c = 0; c < C_; c++) { pr[c] = __fdiv_rn(e[c], s); out[m * C_ + c] = pr[c]; }
        float mp = pr[0];
        for (int c = 1; c < C_; c++) mp = fmaxf(mp, pr[c]);
        float se = 0.f;
        for (int c = 0; c < C_; c++) se += exp_acc(pr[c] - mp);
        int lab = labels[m];
        g_rowloss[m] = (float)(log((double)se)) + mp - pr[lab];
        g_rowcorr[m] = (am == lab) ? 1.f : 0.f;
    }
}

// ---------------- deterministic final reduction ----------------
__global__ __launch_bounds__(256) void finalize_kernel(float* __restrict__ out) {
    __shared__ float sl[256], sa[256];
    int tid = threadIdx.x;
    float l = 0.f, a = 0.f;
    for (int i = tid; i < BT; i += 256) { l += g_rowloss[i]; a += g_rowcorr[i]; }
    sl[tid] = l; sa[tid] = a;
    __syncthreads();
    for (int s = 128; s > 0; s >>= 1) {
        if (tid < s) { sl[tid] += sl[tid + s]; sa[tid] += sa[tid + s]; }
        __syncthreads();
    }
    if (tid == 0) {
        out[BT * C_]     = __fdiv_rn(sl[0], (float)BT);
        out[BT * C_ + 1] = __fdiv_rn(sa[0], (float)BT);
    }
}

// ---------------- launch ----------------
extern "C" void kernel_launch(void* const* d_in, const int* in_sizes, int n_in,
                              void* d_out, int out_size) {
    const float* images = (const float*)d_in[0];
    const int*   labels = (const int*)d_in[1];
    const float* Wx     = (const float*)d_in[2];
    const float* Wh     = (const float*)d_in[3];
    const float* b_lstm = (const float*)d_in[4];
    const float* Wp     = (const float*)d_in[5];
    const float* bp     = (const float*)d_in[6];
    const float* Wc     = (const float*)d_in[7];
    const float* bc     = (const float*)d_in[8];
    float* out = (float*)d_out;

    float *pXpre, *pWrh, *pRh, *pGates;
    cudaGetSymbolAddress((void**)&pXpre,  g_Xpre);
    cudaGetSymbolAddress((void**)&pWrh,   g_Wrh);
    cudaGetSymbolAddress((void**)&pRh,    g_rh);
    cudaGetSymbolAddress((void**)&pGates, g_gates);

    init_kernel<<<1024, 256>>>(Wx, Wh);

    // hoisted time-invariant GEMM: Xpre = images @ Wx[:784] + b_lstm + offset-label row
    {
        dim3 grid(13, BT / 128);   // N=800 -> 13 tiles of 64; M=51200 -> 400 tiles of 128
        mma_gemm<128, 0><<<grid, 256>>>(images, Wx, pXpre, IN_, IN_, b_lstm, Wx, labels, 0);
    }

    for (int t = 0; t < T_; t++) {
        dim3 gB(13, B_ / 64);      // M=1024 -> 16 tiles of 64
        mma_gemm<64, 1><<<gB, 256>>>(pRh, pWrh, pGates, KRH, KRH, pXpre, nullptr, nullptr, t);
        step_kernel<<<B_, 256>>>(Wp, bp, Wc, bc, labels, out, t);
    }

    finalize_kernel<<<1, 256>>>(out);
}

// round 7
// speedup vs baseline: 2.1659x; 1.2315x over previous
#include <cuda_runtime.h>
#include <math.h>
#include <stdint.h>

#define B_   1024
#define T_   50
#define IN_  784
#define NSLOT 128
#define D_   40
#define H_   200
#define R_   4
#define C_   5
#define G4H  800
#define KRH  360
#define BT   (B_*T_)
#define GB   8            // batches per block
#define NBLK (B_/GB)      // 128
#define TPB  512

// ---------------- device globals ----------------
__device__ float g_Xpre[BT * G4H];                 // images@Wx + b + offset row (fp32)
__device__ __align__(16) float g_W4[45*50*32*4];   // packed tf32 Wrh for in-block mma
__device__ float g_WpT[H_ * 164];                  // tf32-rounded Wp
__device__ float g_WcT[KRH * C_];                  // tf32-rounded Wc
__device__ float g_rowloss[BT];
__device__ float g_rowcorr[BT];

__device__ __forceinline__ float tf32r(float x) {
    float y;
    asm("cvt.rna.tf32.f32 %0, %1;" : "=f"(y) : "f"(x));
    return y;
}

// ---------------- precise transcendentals (fast-math immune) ----------------
__device__ __forceinline__ float exp_acc(float x) {
    x = fminf(fmaxf(x, -87.0f), 88.0f);
    float n = rintf(x * 1.44269504088896341f);
    float r = fmaf(n, -0.693359375f, x);
    r = fmaf(n, 2.12194440e-4f, r);
    float z = r * r;
    float p = 1.9875691500e-4f;
    p = fmaf(p, r, 1.3981999507e-3f);
    p = fmaf(p, r, 8.3334519073e-3f);
    p = fmaf(p, r, 4.1665795894e-2f);
    p = fmaf(p, r, 1.6666665459e-1f);
    p = fmaf(p, r, 5.0000001201e-1f);
    float res = fmaf(p, z, r) + 1.0f;
    int i = (int)n;
    float scale = __int_as_float((i + 127) << 23);
    return res * scale;
}
__device__ __forceinline__ float expm1_small(float y) {
    float p = 2.7557319e-7f;
    p = fmaf(p, y, 2.4801587e-5f);
    p = fmaf(p, y, 1.9841270e-4f);
    p = fmaf(p, y, 1.3888889e-3f);
    p = fmaf(p, y, 8.3333333e-3f);
    p = fmaf(p, y, 4.1666667e-2f);
    p = fmaf(p, y, 1.6666667e-1f);
    p = fmaf(p, y, 0.5f);
    p = fmaf(p, y, 1.0f);
    return y * p;
}
__device__ __forceinline__ float tanh_acc(float x) {
    float a = fabsf(x);
    float t;
    if (a < 0.51f) {
        float em1 = expm1_small(2.0f * a);
        t = __fdiv_rn(em1, em1 + 2.0f);
    } else if (a < 9.1f) {
        float e = exp_acc(2.0f * a);
        t = 1.0f - __fdiv_rn(2.0f, e + 1.0f);
    } else {
        t = 1.0f;
    }
    return copysignf(t, x);
}
__device__ __forceinline__ float sigm(float x) {
    float e = exp_acc(-x);
    return __fdiv_rn(1.0f, 1.0f + e);
}

// ---------------- init: build pre-rounded / packed weights ----------------
__global__ void init_kernel(const float* __restrict__ Wx, const float* __restrict__ Wh,
                            const float* __restrict__ Wp, const float* __restrict__ Wc) {
    int idx = blockIdx.x * blockDim.x + threadIdx.x;
    int stride = gridDim.x * blockDim.x;
    // packed Wrh: float4 index = k8*1600 + p*32 + lane; q in [0,4)
    for (int i = idx; i < 45*50*32*4; i += stride) {
        int q = i & 3;
        int lane = (i >> 2) & 31;
        int rest = i >> 7;
        int p = rest % 50, k8 = rest / 50;
        int lr = lane >> 2, lc = lane & 3;
        int row = k8 * 8 + (q & 1) * 4 + lc;         // 0..359 (K index into [r(160);h(200)])
        int col = p * 16 + (q >> 1) * 8 + lr;        // 0..799
        float v = (row < R_*D_) ? Wx[(size_t)(IN_ + C_ + row) * G4H + col]
                                : Wh[(size_t)(row - R_*D_) * G4H + col];
        g_W4[i] = tf32r(v);
    }
    for (int i = idx; i < H_ * 164; i += stride) g_WpT[i] = tf32r(Wp[i]);
    for (int i = idx; i < KRH * C_; i += stride)  g_WcT[i] = tf32r(Wc[i]);
}

// ---------------- tf32 mma helper ----------------
__device__ __forceinline__ void mma_tf32(float& c0, float& c1, float& c2, float& c3,
                                         uint32_t a0, uint32_t a1, uint32_t a2, uint32_t a3,
                                         uint32_t b0, uint32_t b1) {
    asm volatile(
        "mma.sync.aligned.m16n8k8.row.col.f32.tf32.tf32.f32 "
        "{%0,%1,%2,%3}, {%4,%5,%6,%7}, {%8,%9}, {%0,%1,%2,%3};\n"
        : "+f"(c0), "+f"(c1), "+f"(c2), "+f"(c3)
        : "r"(a0), "r"(a1), "r"(a2), "r"(a3), "r"(b0), "r"(b1));
}

// ---------------- hoisted big GEMM (R6, unchanged): Xpre = images@Wx + b + offset row --------
template <int BMT, int EPI>
__global__ __launch_bounds__(256) void mma_gemm(
    const float* __restrict__ A, const float* __restrict__ W, float* __restrict__ Cout,
    int K, int lda,
    const float* __restrict__ e0, const float* __restrict__ e1,
    const int* __restrict__ labs, int t)
{
    constexpr int WARPS_M = BMT / 32;
    constexpr int WARPS_N = 8 / WARPS_M;
    constexpr int WN = 64 / WARPS_N;
    constexpr int NT = WN / 8;
    constexpr int MT = 2;

    __shared__ float As[BMT][36];
    __shared__ float Bs[32][68];

    int tid = threadIdx.x;
    int lane = tid & 31, warp = tid >> 5;
    int wm = warp / WARPS_N, wn = warp % WARPS_N;
    int m0 = blockIdx.y * BMT;
    int n0 = blockIdx.x * 64;
    const int lr = lane >> 2, lc = lane & 3;

    float c[MT][NT][4];
#pragma unroll
    for (int i = 0; i < MT; i++)
#pragma unroll
        for (int j = 0; j < NT; j++)
#pragma unroll
            for (int q = 0; q < 4; q++) c[i][j][q] = 0.f;

    int ar = tid >> 3;
    int ac4 = (tid & 7) * 4;
    int br = tid >> 4;
    int bc4 = (tid & 15) * 4;

    for (int k0 = 0; k0 < K; k0 += 32) {
#pragma unroll
        for (int p = 0; p < BMT / 32; p++) {
            int row = ar + p * 32;
            const float* src = A + (size_t)(m0 + row) * lda + k0 + ac4;
            if (k0 + ac4 + 3 < K) {
                float4 v = *reinterpret_cast<const float4*>(src);
                As[row][ac4 + 0] = tf32r(v.x);
                As[row][ac4 + 1] = tf32r(v.y);
                As[row][ac4 + 2] = tf32r(v.z);
                As[row][ac4 + 3] = tf32r(v.w);
            } else {
#pragma unroll
                for (int i = 0; i < 4; i++) {
                    int k = k0 + ac4 + i;
                    As[row][ac4 + i] = (k < K) ? tf32r(src[i]) : 0.f;
                }
            }
        }
#pragma unroll
        for (int p = 0; p < 2; p++) {
            int krow = k0 + br + p * 16;
            bool ok = (krow < K) && (n0 + bc4 + 3 < G4H);
            float4 v = make_float4(0.f, 0.f, 0.f, 0.f);
            if (ok) v = *reinterpret_cast<const float4*>(W + (size_t)krow * G4H + n0 + bc4);
            Bs[br + p * 16][bc4 + 0] = tf32r(v.x);
            Bs[br + p * 16][bc4 + 1] = tf32r(v.y);
            Bs[br + p * 16][bc4 + 2] = tf32r(v.z);
            Bs[br + p * 16][bc4 + 3] = tf32r(v.w);
        }
        __syncthreads();

#pragma unroll
        for (int k8 = 0; k8 < 4; k8++) {
            int kk = k8 * 8;
            uint32_t a[MT][4];
#pragma unroll
            for (int mt = 0; mt < MT; mt++) {
                int arow = wm * 32 + mt * 16 + lr;
                a[mt][0] = __float_as_uint(As[arow][kk + lc]);
                a[mt][1] = __float_as_uint(As[arow + 8][kk + lc]);
                a[mt][2] = __float_as_uint(As[arow][kk + lc + 4]);
                a[mt][3] = __float_as_uint(As[arow + 8][kk + lc + 4]);
            }
#pragma unroll
            for (int nt = 0; nt < NT; nt++) {
                int bcol = wn * WN + nt * 8 + lr;
                uint32_t b0 = __float_as_uint(Bs[kk + lc][bcol]);
                uint32_t b1 = __float_as_uint(Bs[kk + lc + 4][bcol]);
#pragma unroll
                for (int mt = 0; mt < MT; mt++)
                    mma_tf32(c[mt][nt][0], c[mt][nt][1], c[mt][nt][2], c[mt][nt][3],
                             a[mt][0], a[mt][1], a[mt][2], a[mt][3], b0, b1);
            }
        }
        __syncthreads();
    }

#pragma unroll
    for (int mt = 0; mt < MT; mt++) {
        int row0 = m0 + wm * 32 + mt * 16 + lr;
#pragma unroll
        for (int rr = 0; rr < 2; rr++) {
            int row = row0 + rr * 8;
            int tt = 0, lab = 0;
            if (EPI == 0) {
                tt = row % T_;
                if (tt > 0) lab = labs[row - 1];
            }
#pragma unroll
            for (int nt = 0; nt < NT; nt++) {
                int col = n0 + wn * WN + nt * 8 + 2 * lc;
#pragma unroll
                for (int cc = 0; cc < 2; cc++) {
                    int cg = col + cc;
                    if (cg < G4H) {
                        float v = c[mt][nt][rr * 2 + cc];
                        if (EPI == 0) {
                            v += e0[cg];
                            if (tt > 0) v += tf32r(e1[(size_t)(IN_ + lab) * G4H + cg]);
                        } else {
                            v += e0[(size_t)(row * T_ + t) * G4H + cg];
                        }
                        Cout[(size_t)row * G4H + cg] = v;
                    }
                }
            }
        }
    }
}

// ---------------- fused persistent recurrence kernel ----------------
// smem float offsets
#define OFF_SM   0                    // GB*5120 = 40960
#define OFF_RHT  40960                // GB*361  = 2888 (tf32-rounded [r(160),h(200),pad])
#define OFF_GU   43848                // 6400: gates[GB*800]; later swr(4096)+Mnorm(1024)+skn(1280)
#define OFF_SWR  (OFF_GU)
#define OFF_MN   (OFF_GU + 4096)
#define OFF_SKN  (OFF_GU + 5120)
#define OFF_WRO  50248                // GB*512 = 4096 (raw prev read weights)
#define OFF_WU   54344                // GB*128 = 1024
#define OFF_SKT  55368                // GB*160 = 1280 (keys: raw then tf32-rounded)
#define OFF_KN   56648                // 32 key norms
#define OFF_SSIG 56680                // 32
#define OFF_SLOG 56712                // 40
#define OFF_LU   56752                // 32 (ints)
#define SMEM_FLOATS 56784
#define SMEM_BYTES  (SMEM_FLOATS * 4)

__global__ __launch_bounds__(TPB, 1) void fused_kernel(
    const float* __restrict__ bp, const float* __restrict__ bc,
    const int* __restrict__ labels, float* __restrict__ out)
{
    extern __shared__ float S[];
    int tid = threadIdx.x;
    int lane = tid & 31, warp = tid >> 5;
    int bb = blockIdx.x * GB;
    int* s_luI = (int*)(S + OFF_LU);

    float c_reg[4] = {0.f, 0.f, 0.f, 0.f};   // LSTM cell state, thread-owned

    // ---- state init ----
    for (int i = tid; i < GB * 5120; i += TPB) S[OFF_SM + i] = 1e-6f;
    for (int i = tid; i < GB * 361; i += TPB) {
        int j = i % 361;
        S[OFF_RHT + i] = (j < R_*D_) ? tf32r(1e-6f) : 0.f;
    }
    for (int i = tid; i < GB * NSLOT; i += TPB) S[OFF_WU + i] = ((i & 127) == 0) ? 1.f : 0.f;
    for (int i = tid; i < GB * 512; i += TPB)   S[OFF_WRO + i] = ((i & 127) == 0) ? 1.f : 0.f;
    __syncthreads();

    for (int t = 0; t < T_; t++) {
        // ---- A: gates GEMM [8x360]@[360x800] via mma, + Xpre epilogue ----
        {
            int lr = lane >> 2, lc = lane & 3;
            const float* rhRow = S + OFF_RHT + lr * 361;
            const float4* W4 = reinterpret_cast<const float4*>(g_W4);
            for (int p = warp; p < 50; p += 16) {
                float c00 = 0.f, c01 = 0.f, c02 = 0.f, c03 = 0.f;
                float c10 = 0.f, c11 = 0.f, c12 = 0.f, c13 = 0.f;
                const float4* wp4 = W4 + p * 32 + lane;
#pragma unroll 5
                for (int k8 = 0; k8 < 45; k8++) {
                    float4 w = wp4[k8 * 1600];
                    uint32_t a0 = __float_as_uint(rhRow[k8 * 8 + lc]);
                    uint32_t a2 = __float_as_uint(rhRow[k8 * 8 + 4 + lc]);
                    mma_tf32(c00, c01, c02, c03, a0, 0u, a2, 0u,
                             __float_as_uint(w.x), __float_as_uint(w.y));
                    mma_tf32(c10, c11, c12, c13, a0, 0u, a2, 0u,
                             __float_as_uint(w.z), __float_as_uint(w.w));
                }
                int col0 = p * 16 + 2 * lc;
                const float* xp = g_Xpre + ((size_t)(bb + lr) * T_ + t) * G4H;
                float* gr = S + OFF_GU + lr * 800;
                gr[col0]     = c00 + xp[col0];
                gr[col0 + 1] = c01 + xp[col0 + 1];
                gr[col0 + 8] = c10 + xp[col0 + 8];
                gr[col0 + 9] = c11 + xp[col0 + 9];
            }
        }
        __syncthreads();

        // ---- B: LSTM pointwise (1600 units) ----
#pragma unroll
        for (int s = 0; s < 4; s++) {
            int i = tid + s * TPB;
            if (i < GB * H_) {
                int g = i / H_, u = i - g * H_;
                const float* gg = S + OFF_GU + g * 800;
                float ig = gg[u], fg = gg[200 + u], gz = gg[400 + u], og = gg[600 + u];
                float c_new = sigm(fg) * c_reg[s] + sigm(ig) * tanh_acc(gz);
                c_reg[s] = c_new;
                float h = sigm(og) * tanh_acc(c_new);
                S[OFF_RHT + g * 361 + R_*D_ + u] = tf32r(h);
            }
        }
        __syncthreads();

        // ---- C: keys (raw) + sigma; M row norms ----
#pragma unroll
        for (int s = 0; s < 3; s++) {
            int i = tid + s * TPB;
            if (i < GB * 164) {
                int g = i / 164, j = i - g * 164;
                const float* hT = S + OFF_RHT + g * 361 + R_*D_;
                float a0 = 0.f, a1 = 0.f, a2 = 0.f, a3 = 0.f;
                for (int u = 0; u < H_; u += 4) {
                    a0 = fmaf(hT[u],     g_WpT[(u)     * 164 + j], a0);
                    a1 = fmaf(hT[u + 1], g_WpT[(u + 1) * 164 + j], a1);
                    a2 = fmaf(hT[u + 2], g_WpT[(u + 2) * 164 + j], a2);
                    a3 = fmaf(hT[u + 3], g_WpT[(u + 3) * 164 + j], a3);
                }
                float acc = ((a0 + a1) + (a2 + a3)) + bp[j];
                int r = j / 41, w = j - r * 41;
                if (w < D_) S[OFF_SKT + g * 160 + r * 40 + w] = tanh_acc(acc);
                else        S[OFF_SSIG + g * 4 + r] = sigm(acc);
            }
        }
#pragma unroll
        for (int s = 0; s < 2; s++) {
            int p = tid + s * TPB;
            int g = p >> 7, n = p & 127;
            const float* Mr = S + OFF_SM + g * 5120 + n * 40;
            float ss = 0.f;
            for (int d = 0; d < D_; d++) ss = fmaf(Mr[d], Mr[d], ss);
            S[OFF_MN + p] = __fsqrt_rn(ss) + 1e-8f;
        }
        __syncthreads();

        // ---- D: key norms (tid<32) + LU selection (warps 8..15) ----
        if (tid < 32) {
            int g = tid >> 2, r = tid & 3;
            const float* kk = S + OFF_SKT + g * 160 + r * 40;
            float ss = 0.f;
            for (int d = 0; d < D_; d++) ss = fmaf(kk[d], kk[d], ss);
            S[OFF_KN + tid] = __fsqrt_rn(ss) + 1e-8f;
        } else if (warp >= 8) {
            int g = warp - 8;
            const float* wu = S + OFF_WU + g * NSLOT;
            float v0 = wu[lane], v1 = wu[lane + 32], v2 = wu[lane + 64], v3 = wu[lane + 96];
            int i0 = lane, i1 = lane + 32, i2 = lane + 64, i3 = lane + 96;
#pragma unroll
            for (int s = 0; s < R_; s++) {
                float bv = v0; int bi = i0;
                if (v1 < bv || (v1 == bv && i1 < bi)) { bv = v1; bi = i1; }
                if (v2 < bv || (v2 == bv && i2 < bi)) { bv = v2; bi = i2; }
                if (v3 < bv || (v3 == bv && i3 < bi)) { bv = v3; bi = i3; }
#pragma unroll
                for (int o = 16; o > 0; o >>= 1) {
                    float ov = __shfl_xor_sync(0xffffffffu, bv, o);
                    int   oi = __shfl_xor_sync(0xffffffffu, bi, o);
                    if (ov < bv || (ov == bv && oi < bi)) { bv = ov; bi = oi; }
                }
                if (lane == 0) s_luI[g * 4 + s] = bi;
                if      (bi == i0) v0 = 3.0e38f;
                else if (bi == i1) v1 = 3.0e38f;
                else if (bi == i2) v2 = 3.0e38f;
                else if (bi == i3) v3 = 3.0e38f;
            }
        }
        __syncthreads();

        // ---- E: round keys; build skn (normalized, rounded) ----
#pragma unroll
        for (int s = 0; s < 3; s++) {
            int i = tid + s * TPB;
            if (i < GB * 160) {
                int g = i / 160, j = i - g * 160;
                int r = j / 40;
                float raw = S[OFF_SKT + i];
                float nrm = S[OFF_KN + g * 4 + r];
                S[OFF_SKN + i] = tf32r(__fdiv_rn(raw, nrm));
                S[OFF_SKT + i] = tf32r(raw);
            }
        }
        __syncthreads();

        // ---- F: cosine logits ----
#pragma unroll
        for (int s = 0; s < 2; s++) {
            int p = tid + s * TPB;
            int g = p >> 7, n = p & 127;
            const float* Mr = S + OFF_SM + g * 5120 + n * 40;
            const float* kn = S + OFF_SKN + g * 160;
            float rinv = __fdiv_rn(1.f, S[OFF_MN + p]);
            float a0 = 0.f, a1 = 0.f, a2 = 0.f, a3 = 0.f;
            for (int d = 0; d < D_; d++) {
                float mn = tf32r(Mr[d] * rinv);
                a0 = fmaf(mn, kn[d],       a0);
                a1 = fmaf(mn, kn[40 + d],  a1);
                a2 = fmaf(mn, kn[80 + d],  a2);
                a3 = fmaf(mn, kn[120 + d], a3);
            }
            float* sw = S + OFF_SWR + g * 512;
            sw[n] = a0; sw[128 + n] = a1; sw[256 + n] = a2; sw[384 + n] = a3;
        }
        __syncthreads();

        // ---- G: softmax per (g,r) row ----
        for (int row = warp; row < GB * R_; row += 16) {
            int g = row >> 2, r = row & 3;
            float* sw = S + OFF_SWR + g * 512 + r * 128;
            float v0 = sw[lane], v1 = sw[lane + 32], v2 = sw[lane + 64], v3 = sw[lane + 96];
            float mx = fmaxf(fmaxf(v0, v1), fmaxf(v2, v3));
            for (int o = 16; o > 0; o >>= 1) mx = fmaxf(mx, __shfl_xor_sync(0xffffffffu, mx, o));
            float e0 = exp_acc(v0 - mx), e1 = exp_acc(v1 - mx), e2 = exp_acc(v2 - mx), e3 = exp_acc(v3 - mx);
            float ssum = e0 + e1 + e2 + e3;
            for (int o = 16; o > 0; o >>= 1) ssum += __shfl_xor_sync(0xffffffffu, ssum, o);
            sw[lane]      = __fdiv_rn(e0, ssum);
            sw[lane + 32] = __fdiv_rn(e1, ssum);
            sw[lane + 64] = __fdiv_rn(e2, ssum);
            sw[lane + 96] = __fdiv_rn(e3, ssum);
        }
        __syncthreads();

        // ---- H: usage update + wrOld<-swr + memory write einsum  (per (g,n)) ----
#pragma unroll
        for (int s = 0; s < 2; s++) {
            int p = tid + s * TPB;
            int g = p >> 7, n = p & 127;
            float* wro = S + OFF_WRO + g * 512;
            float* sw  = S + OFF_SWR + g * 512;
            int lu0 = s_luI[g*4], lu1 = s_luI[g*4+1], lu2 = s_luI[g*4+2], lu3 = s_luI[g*4+3];
            float wlu = (n == lu0 || n == lu1 || n == lu2 || n == lu3) ? 1.f : 0.f;
            float sg0 = S[OFF_SSIG + g*4], sg1 = S[OFF_SSIG + g*4+1];
            float sg2 = S[OFF_SSIG + g*4+2], sg3 = S[OFF_SSIG + g*4+3];
            float wo0 = wro[n], wo1 = wro[128+n], wo2 = wro[256+n], wo3 = wro[384+n];
            float ww0 = sg0 * wo0 + (1.f - sg0) * wlu;
            float ww1 = sg1 * wo1 + (1.f - sg1) * wlu;
            float ww2 = sg2 * wo2 + (1.f - sg2) * wlu;
            float ww3 = sg3 * wo3 + (1.f - sg3) * wlu;
            float sr0 = sw[n], sr1 = sw[128+n], sr2 = sw[256+n], sr3 = sw[384+n];
            float v = 0.95f * S[OFF_WU + p];
            v += sr0 + ww0; v += sr1 + ww1; v += sr2 + ww2; v += sr3 + ww3;
            S[OFF_WU + p] = v;
            wro[n] = sr0; wro[128+n] = sr1; wro[256+n] = sr2; wro[384+n] = sr3;
            float wt0 = tf32r(ww0), wt1 = tf32r(ww1), wt2 = tf32r(ww2), wt3 = tf32r(ww3);
            float* Mr = S + OFF_SM + g * 5120 + n * 40;
            const float* kT = S + OFF_SKT + g * 160;
            bool zero_base = (n == lu3);
            for (int d = 0; d < D_; d++) {
                float base = zero_base ? 0.f : Mr[d];
                float add = 0.f;
                add = fmaf(wt0, kT[d],       add);
                add = fmaf(wt1, kT[40 + d],  add);
                add = fmaf(wt2, kT[80 + d],  add);
                add = fmaf(wt3, kT[120 + d], add);
                Mr[d] = base + add;
            }
        }
        __syncthreads();

        // ---- I: round swr in place (for read einsum / persisted wr stays raw in wrOld) ----
        for (int i = tid; i < GB * 512; i += TPB) S[OFF_SWR + i] = tf32r(S[OFF_SWR + i]);
        __syncthreads();

        // ---- J: read einsum -> rhT r-part ----
#pragma unroll
        for (int s = 0; s < 3; s++) {
            int i = tid + s * TPB;
            if (i < GB * R_ * D_) {
                int g = i / 160, j = i - g * 160;
                int r = j / 40, d = j - r * 40;
                const float* sw = S + OFF_SWR + g * 512 + r * 128;
                const float* Mc = S + OFF_SM + g * 5120 + d;
                float a0 = 0.f, a1 = 0.f, a2 = 0.f, a3 = 0.f;
                for (int n = 0; n < NSLOT; n += 4) {
                    a0 = fmaf(sw[n],     tf32r(Mc[(n)     * 40]), a0);
                    a1 = fmaf(sw[n + 1], tf32r(Mc[(n + 1) * 40]), a1);
                    a2 = fmaf(sw[n + 2], tf32r(Mc[(n + 2) * 40]), a2);
                    a3 = fmaf(sw[n + 3], tf32r(Mc[(n + 3) * 40]), a3);
                }
                float acc = (a0 + a1) + (a2 + a3);
                S[OFF_RHT + g * 361 + j] = tf32r(acc);
            }
        }
        __syncthreads();

        // ---- K: classifier (40 outputs, warp-reduce) ----
        for (int o = warp; o < GB * C_; o += 16) {
            int g = o / C_, cl = o - g * C_;
            const float* rh = S + OFF_RHT + g * 361;
            float acc = 0.f;
            for (int j = lane; j < KRH; j += 32) {
                float v = (j < H_) ? rh[R_*D_ + j] : rh[j - H_];
                acc = fmaf(v, g_WcT[j * C_ + cl], acc);
            }
#pragma unroll
            for (int o2 = 16; o2 > 0; o2 >>= 1) acc += __shfl_xor_sync(0xffffffffu, acc, o2);
            if (lane == 0) S[OFF_SLOG + o] = acc + bc[cl];
        }
        __syncthreads();

        // ---- L: probs + loss/acc rows ----
        if (tid < GB) {
            int g = tid;
            int m = (bb + g) * T_ + t;
            const float* lg = S + OFF_SLOG + g * C_;
            float mx = lg[0]; int am = 0;
            for (int c = 1; c < C_; c++) if (lg[c] > mx) { mx = lg[c]; am = c; }
            float e[C_], ssum = 0.f;
            for (int c = 0; c < C_; c++) { e[c] = exp_acc(lg[c] - mx); ssum += e[c]; }
            float pr[C_];
            for (int c = 0; c < C_; c++) { pr[c] = __fdiv_rn(e[c], ssum); out[m * C_ + c] = pr[c]; }
            float mp = pr[0];
            for (int c = 1; c < C_; c++) mp = fmaxf(mp, pr[c]);
            float se = 0.f;
            for (int c = 0; c < C_; c++) se += exp_acc(pr[c] - mp);
            int lab = labels[m];
            g_rowloss[m] = (float)(log((double)se)) + mp - pr[lab];
            g_rowcorr[m] = (am == lab) ? 1.f : 0.f;
        }
        __syncthreads();
    }
}

// ---------------- deterministic final reduction ----------------
__global__ __launch_bounds__(256) void finalize_kernel(float* __restrict__ out) {
    __shared__ float sl[256], sa[256];
    int tid = threadIdx.x;
    float l = 0.f, a = 0.f;
    for (int i = tid; i < BT; i += 256) { l += g_rowloss[i]; a += g_rowcorr[i]; }
    sl[tid] = l; sa[tid] = a;
    __syncthreads();
    for (int s = 128; s > 0; s >>= 1) {
        if (tid < s) { sl[tid] += sl[tid + s]; sa[tid] += sa[tid + s]; }
        __syncthreads();
    }
    if (tid == 0) {
        out[BT * C_]     = __fdiv_rn(sl[0], (float)BT);
        out[BT * C_ + 1] = __fdiv_rn(sa[0], (float)BT);
    }
}

// ---------------- launch ----------------
extern "C" void kernel_launch(void* const* d_in, const int* in_sizes, int n_in,
                              void* d_out, int out_size) {
    const float* images = (const float*)d_in[0];
    const int*   labels = (const int*)d_in[1];
    const float* Wx     = (const float*)d_in[2];
    const float* Wh     = (const float*)d_in[3];
    const float* b_lstm = (const float*)d_in[4];
    const float* Wp     = (const float*)d_in[5];
    const float* bp     = (const float*)d_in[6];
    const float* Wc     = (const float*)d_in[7];
    const float* bc     = (const float*)d_in[8];
    float* out = (float*)d_out;

    float* pXpre;
    cudaGetSymbolAddress((void**)&pXpre, g_Xpre);

    cudaFuncSetAttribute(fused_kernel, cudaFuncAttributeMaxDynamicSharedMemorySize, SMEM_BYTES);

    init_kernel<<<320, 256>>>(Wx, Wh, Wp, Wc);

    {
        dim3 grid(13, BT / 128);
        mma_gemm<128, 0><<<grid, 256>>>(images, Wx, pXpre, IN_, IN_, b_lstm, Wx, labels, 0);
    }

    fused_kernel<<<NBLK, TPB, SMEM_BYTES>>>(bp, bc, labels, out);

    finalize_kernel<<<1, 256>>>(out);
}

// round 8
// speedup vs baseline: 2.9497x; 1.3619x over previous
#include <cuda_runtime.h>
#include <math.h>
#include <stdint.h>

#define B_   1024
#define T_   50
#define IN_  784
#define NSLOT 128
#define D_   40
#define H_   200
#define R_   4
#define C_   5
#define G4H  800
#define KRH  360
#define BT   (B_*T_)
#define GB   8            // batches per block
#define NBLK (B_/GB)      // 128
#define TPB  512
#define MSTR 41           // padded M row stride (conflict-free: 41 mod 32 = 9, coprime 32)

// ---------------- device globals ----------------
__device__ float g_Xpre[BT * G4H];                 // images@Wx + b + offset row (fp32)
__device__ __align__(16) float g_W4[45*50*32*4];   // packed tf32 Wrh for in-block mma
__device__ __align__(16) float g_WpT[H_ * 164];    // tf32-rounded Wp (row-major, 164=41*float4)
__device__ float g_WcT[KRH * C_];                  // tf32-rounded Wc
__device__ __align__(16) float g_Wxr[IN_ * G4H];   // tf32-rounded Wx rows [0,784)
__device__ float g_rowloss[BT];
__device__ float g_rowcorr[BT];

__device__ __forceinline__ float tf32r(float x) {
    float y;
    asm("cvt.rna.tf32.f32 %0, %1;" : "=f"(y) : "f"(x));
    return y;
}

// ---------------- precise transcendentals (fast-math immune) ----------------
__device__ __forceinline__ float exp_acc(float x) {
    x = fminf(fmaxf(x, -87.0f), 88.0f);
    float n = rintf(x * 1.44269504088896341f);
    float r = fmaf(n, -0.693359375f, x);
    r = fmaf(n, 2.12194440e-4f, r);
    float z = r * r;
    float p = 1.9875691500e-4f;
    p = fmaf(p, r, 1.3981999507e-3f);
    p = fmaf(p, r, 8.3334519073e-3f);
    p = fmaf(p, r, 4.1665795894e-2f);
    p = fmaf(p, r, 1.6666665459e-1f);
    p = fmaf(p, r, 5.0000001201e-1f);
    float res = fmaf(p, z, r) + 1.0f;
    int i = (int)n;
    float scale = __int_as_float((i + 127) << 23);
    return res * scale;
}
__device__ __forceinline__ float expm1_small(float y) {
    float p = 2.7557319e-7f;
    p = fmaf(p, y, 2.4801587e-5f);
    p = fmaf(p, y, 1.9841270e-4f);
    p = fmaf(p, y, 1.3888889e-3f);
    p = fmaf(p, y, 8.3333333e-3f);
    p = fmaf(p, y, 4.1666667e-2f);
    p = fmaf(p, y, 1.6666667e-1f);
    p = fmaf(p, y, 0.5f);
    p = fmaf(p, y, 1.0f);
    return y * p;
}
__device__ __forceinline__ float tanh_acc(float x) {
    float a = fabsf(x);
    float t;
    if (a < 0.51f) {
        float em1 = expm1_small(2.0f * a);
        t = __fdiv_rn(em1, em1 + 2.0f);
    } else if (a < 9.1f) {
        float e = exp_acc(2.0f * a);
        t = 1.0f - __fdiv_rn(2.0f, e + 1.0f);
    } else {
        t = 1.0f;
    }
    return copysignf(t, x);
}
__device__ __forceinline__ float sigm(float x) {
    float e = exp_acc(-x);
    return __fdiv_rn(1.0f, 1.0f + e);
}

// ---------------- init: build pre-rounded / packed weights ----------------
__global__ void init_kernel(const float* __restrict__ Wx, const float* __restrict__ Wh,
                            const float* __restrict__ Wp, const float* __restrict__ Wc) {
    int idx = blockIdx.x * blockDim.x + threadIdx.x;
    int stride = gridDim.x * blockDim.x;
    for (int i = idx; i < 45*50*32*4; i += stride) {
        int q = i & 3;
        int lane = (i >> 2) & 31;
        int rest = i >> 7;
        int p = rest % 50, k8 = rest / 50;
        int lr = lane >> 2, lc = lane & 3;
        int row = k8 * 8 + (q & 1) * 4 + lc;
        int col = p * 16 + (q >> 1) * 8 + lr;
        float v = (row < R_*D_) ? Wx[(size_t)(IN_ + C_ + row) * G4H + col]
                                : Wh[(size_t)(row - R_*D_) * G4H + col];
        g_W4[i] = tf32r(v);
    }
    for (int i = idx; i < H_ * 164; i += stride) g_WpT[i] = tf32r(Wp[i]);
    for (int i = idx; i < KRH * C_; i += stride)  g_WcT[i] = tf32r(Wc[i]);
    for (int i = idx; i < IN_ * G4H; i += stride) g_Wxr[i] = tf32r(Wx[i]);
}

// ---------------- tf32 mma helper ----------------
__device__ __forceinline__ void mma_tf32(float& c0, float& c1, float& c2, float& c3,
                                         uint32_t a0, uint32_t a1, uint32_t a2, uint32_t a3,
                                         uint32_t b0, uint32_t b1) {
    asm volatile(
        "mma.sync.aligned.m16n8k8.row.col.f32.tf32.tf32.f32 "
        "{%0,%1,%2,%3}, {%4,%5,%6,%7}, {%8,%9}, {%0,%1,%2,%3};\n"
        : "+f"(c0), "+f"(c1), "+f"(c2), "+f"(c3)
        : "r"(a0), "r"(a1), "r"(a2), "r"(a3), "r"(b0), "r"(b1));
}

// ---------------- gemm0: Xpre = images @ Wx[:784] + b + offset row (cp.async 2-stage) ------
#define NKT 25   // ceil(784/32)
__global__ __launch_bounds__(256) void gemm0_kernel(
    const float* __restrict__ A, const float* __restrict__ WxFull,
    const float* __restrict__ b_lstm, const int* __restrict__ labs,
    float* __restrict__ Cout)
{
    __shared__ float As[2][128][36];
    __shared__ float Bs[2][32][68];
    int tid = threadIdx.x, lane = tid & 31, warp = tid >> 5;
    int wm = warp >> 1, wn = warp & 1;        // WARPS_M=4, WARPS_N=2, WN=32, NT=4, MT=2
    int m0 = blockIdx.y * 128, n0 = blockIdx.x * 64;
    int lr = lane >> 2, lc = lane & 3;
    float c[2][4][4];
#pragma unroll
    for (int i = 0; i < 2; i++)
#pragma unroll
        for (int j = 0; j < 4; j++)
#pragma unroll
            for (int q = 0; q < 4; q++) c[i][j][q] = 0.f;

#define G0_ISSUE(IT) do {                                                       \
    int st_ = (IT) & 1;                                                         \
    int k0_ = (IT) * 32;                                                        \
    _Pragma("unroll")                                                           \
    for (int i_ = 0; i_ < 4; i_++) {                                            \
        int e_ = tid + i_ * 256;                                                \
        int row_ = e_ >> 3, c4_ = (e_ & 7) * 4;                                 \
        uint32_t sz_ = (k0_ + c4_ < IN_) ? 16u : 0u;                            \
        const float* src_ = A + (size_t)(m0 + row_) * IN_ + (sz_ ? (k0_ + c4_) : 0); \
        uint32_t da_ = (uint32_t)__cvta_generic_to_shared(&As[st_][row_][c4_]); \
        asm volatile("cp.async.ca.shared.global [%0], [%1], 16, %2;" :: "r"(da_), "l"(src_), "r"(sz_)); \
    }                                                                           \
    _Pragma("unroll")                                                           \
    for (int i_ = 0; i_ < 2; i_++) {                                            \
        int e_ = tid + i_ * 256;                                                \
        int row_ = e_ >> 4, c4_ = (e_ & 15) * 4;                                \
        int krow_ = k0_ + row_;                                                 \
        int col_ = n0 + c4_;                                                    \
        uint32_t sz_ = (krow_ < IN_ && col_ < G4H) ? 16u : 0u;                  \
        const float* src_ = g_Wxr + (sz_ ? ((size_t)krow_ * G4H + col_) : 0);   \
        uint32_t da_ = (uint32_t)__cvta_generic_to_shared(&Bs[st_][row_][c4_]); \
        asm volatile("cp.async.ca.shared.global [%0], [%1], 16, %2;" :: "r"(da_), "l"(src_), "r"(sz_)); \
    }                                                                           \
    asm volatile("cp.async.commit_group;");                                     \
} while (0)

    G0_ISSUE(0);
    for (int it = 0; it < NKT; it++) {
        if (it + 1 < NKT) {
            G0_ISSUE(it + 1);
            asm volatile("cp.async.wait_group 1;");
        } else {
            asm volatile("cp.async.wait_group 0;");
        }
        __syncthreads();
        int st = it & 1;
#pragma unroll
        for (int k8 = 0; k8 < 4; k8++) {
            int kk = k8 * 8;
            uint32_t a[2][4];
#pragma unroll
            for (int mt = 0; mt < 2; mt++) {
                int arow = wm * 32 + mt * 16 + lr;
                a[mt][0] = __float_as_uint(tf32r(As[st][arow][kk + lc]));
                a[mt][1] = __float_as_uint(tf32r(As[st][arow + 8][kk + lc]));
                a[mt][2] = __float_as_uint(tf32r(As[st][arow][kk + lc + 4]));
                a[mt][3] = __float_as_uint(tf32r(As[st][arow + 8][kk + lc + 4]));
            }
#pragma unroll
            for (int nt = 0; nt < 4; nt++) {
                int bcol = wn * 32 + nt * 8 + lr;
                uint32_t b0 = __float_as_uint(Bs[st][kk + lc][bcol]);
                uint32_t b1 = __float_as_uint(Bs[st][kk + lc + 4][bcol]);
#pragma unroll
                for (int mt = 0; mt < 2; mt++)
                    mma_tf32(c[mt][nt][0], c[mt][nt][1], c[mt][nt][2], c[mt][nt][3],
                             a[mt][0], a[mt][1], a[mt][2], a[mt][3], b0, b1);
            }
        }
        __syncthreads();
    }

#pragma unroll
    for (int mt = 0; mt < 2; mt++) {
        int row0 = m0 + wm * 32 + mt * 16 + lr;
#pragma unroll
        for (int rr = 0; rr < 2; rr++) {
            int row = row0 + rr * 8;
            int tt = row % T_;
            int lab = (tt > 0) ? labs[row - 1] : 0;
#pragma unroll
            for (int nt = 0; nt < 4; nt++) {
                int col = n0 + wn * 32 + nt * 8 + 2 * lc;
#pragma unroll
                for (int cc = 0; cc < 2; cc++) {
                    int cg = col + cc;
                    if (cg < G4H) {
                        float v = c[mt][nt][rr * 2 + cc];
                        v += b_lstm[cg];
                        if (tt > 0) v += tf32r(WxFull[(size_t)(IN_ + lab) * G4H + cg]);
                        Cout[(size_t)row * G4H + cg] = v;
                    }
                }
            }
        }
    }
}

// ---------------- fused persistent recurrence kernel ----------------
// smem float offsets (stride-41 padded M)
#define OFF_SM   0                      // GB*5248 = 41984
#define OFF_RHT  41984                  // GB*361 = 2888 -> 44872
#define OFF_GU   44872                  // 6400 gates; union: SWR+MN+SKN
#define OFF_SWR  (OFF_GU)               // 4096
#define OFF_MN   (OFF_GU + 4096)        // 1024
#define OFF_SKN  (OFF_GU + 5120)        // 1280
#define OFF_WRO  51272                  // 4096 -> 55368
#define OFF_WU   55368                  // 1024 -> 56392
#define OFF_SKT  56392                  // 1280 -> 57672
#define OFF_KN   57672                  // 32
#define OFF_SSIG 57704                  // 32
#define OFF_SLOG 57736                  // 40
#define OFF_LU   57776                  // 32 ints
#define SMEM_FLOATS 57808
#define SMEM_BYTES  (SMEM_FLOATS * 4)   // 231232 <= 232448

__global__ __launch_bounds__(TPB, 1) void fused_kernel(
    const float* __restrict__ bp, const float* __restrict__ bc,
    const int* __restrict__ labels, float* __restrict__ out)
{
    extern __shared__ float S[];
    int tid = threadIdx.x;
    int lane = tid & 31, warp = tid >> 5;
    int bb = blockIdx.x * GB;
    int* s_luI = (int*)(S + OFF_LU);

    float c_reg[4] = {0.f, 0.f, 0.f, 0.f};

    // ---- state init ----
    for (int i = tid; i < GB * NSLOT * MSTR; i += TPB) S[OFF_SM + i] = 1e-6f;
    for (int i = tid; i < GB * 361; i += TPB) {
        int j = i % 361;
        S[OFF_RHT + i] = (j < R_*D_) ? tf32r(1e-6f) : 0.f;
    }
    for (int i = tid; i < GB * NSLOT; i += TPB) S[OFF_WU + i] = ((i & 127) == 0) ? 1.f : 0.f;
    for (int i = tid; i < GB * 512; i += TPB)   S[OFF_WRO + i] = ((i & 127) == 0) ? 1.f : 0.f;
    __syncthreads();

    for (int t = 0; t < T_; t++) {
        // ---- A: gates GEMM [8x360]@[360x800] via mma, + Xpre epilogue ----
        {
            int lr = lane >> 2, lc = lane & 3;
            const float* rhRow = S + OFF_RHT + lr * 361;
            const float4* W4 = reinterpret_cast<const float4*>(g_W4);
            for (int p = warp; p < 50; p += 16) {
                float c00 = 0.f, c01 = 0.f, c02 = 0.f, c03 = 0.f;
                float c10 = 0.f, c11 = 0.f, c12 = 0.f, c13 = 0.f;
                const float4* wp4 = W4 + p * 32 + lane;
#pragma unroll 5
                for (int k8 = 0; k8 < 45; k8++) {
                    float4 w = wp4[k8 * 1600];
                    uint32_t a0 = __float_as_uint(rhRow[k8 * 8 + lc]);
                    uint32_t a2 = __float_as_uint(rhRow[k8 * 8 + 4 + lc]);
                    mma_tf32(c00, c01, c02, c03, a0, 0u, a2, 0u,
                             __float_as_uint(w.x), __float_as_uint(w.y));
                    mma_tf32(c10, c11, c12, c13, a0, 0u, a2, 0u,
                             __float_as_uint(w.z), __float_as_uint(w.w));
                }
                int col0 = p * 16 + 2 * lc;
                const float* xp = g_Xpre + ((size_t)(bb + lr) * T_ + t) * G4H;
                float* gr = S + OFF_GU + lr * 800;
                gr[col0]     = c00 + xp[col0];
                gr[col0 + 1] = c01 + xp[col0 + 1];
                gr[col0 + 8] = c10 + xp[col0 + 8];
                gr[col0 + 9] = c11 + xp[col0 + 9];
            }
        }
        __syncthreads();

        // ---- B: LSTM pointwise ----
#pragma unroll
        for (int s = 0; s < 4; s++) {
            int i = tid + s * TPB;
            if (i < GB * H_) {
                int g = i / H_, u = i - g * H_;
                const float* gg = S + OFF_GU + g * 800;
                float ig = gg[u], fg = gg[200 + u], gz = gg[400 + u], og = gg[600 + u];
                float c_new = sigm(fg) * c_reg[s] + sigm(ig) * tanh_acc(gz);
                c_reg[s] = c_new;
                float h = sigm(og) * tanh_acc(c_new);
                S[OFF_RHT + g * 361 + R_*D_ + u] = tf32r(h);
            }
        }
        __syncthreads();

        // ---- C: M row norms (all threads, conflict-free stride 41) + keys via float4 Wp ----
#pragma unroll
        for (int s = 0; s < 2; s++) {
            int p = tid + s * TPB;
            int g = p >> 7, n = p & 127;
            const float* Mr = S + OFF_SM + g * NSLOT * MSTR + n * MSTR;
            float ss = 0.f;
            for (int d = 0; d < D_; d++) ss = fmaf(Mr[d], Mr[d], ss);
            S[OFF_MN + p] = __fsqrt_rn(ss) + 1e-8f;
        }
        if (tid < GB * 41) {
            int g = tid / 41, q4 = tid - g * 41;
            const float4* wrow = reinterpret_cast<const float4*>(g_WpT) + q4;
            const float* hT = S + OFF_RHT + g * 361 + R_*D_;
            float4 s0 = {0,0,0,0}, s1 = {0,0,0,0}, s2 = {0,0,0,0}, s3 = {0,0,0,0};
            for (int u = 0; u < H_; u += 4) {
                float h0 = hT[u], h1 = hT[u+1], h2 = hT[u+2], h3 = hT[u+3];
                float4 w0 = wrow[(u)   * 41];
                float4 w1 = wrow[(u+1) * 41];
                float4 w2 = wrow[(u+2) * 41];
                float4 w3 = wrow[(u+3) * 41];
                s0.x = fmaf(h0, w0.x, s0.x); s0.y = fmaf(h0, w0.y, s0.y);
                s0.z = fmaf(h0, w0.z, s0.z); s0.w = fmaf(h0, w0.w, s0.w);
                s1.x = fmaf(h1, w1.x, s1.x); s1.y = fmaf(h1, w1.y, s1.y);
                s1.z = fmaf(h1, w1.z, s1.z); s1.w = fmaf(h1, w1.w, s1.w);
                s2.x = fmaf(h2, w2.x, s2.x); s2.y = fmaf(h2, w2.y, s2.y);
                s2.z = fmaf(h2, w2.z, s2.z); s2.w = fmaf(h2, w2.w, s2.w);
                s3.x = fmaf(h3, w3.x, s3.x); s3.y = fmaf(h3, w3.y, s3.y);
                s3.z = fmaf(h3, w3.z, s3.z); s3.w = fmaf(h3, w3.w, s3.w);
            }
            float rsum[4];
            rsum[0] = (s0.x + s1.x) + (s2.x + s3.x);
            rsum[1] = (s0.y + s1.y) + (s2.y + s3.y);
            rsum[2] = (s0.z + s1.z) + (s2.z + s3.z);
            rsum[3] = (s0.w + s1.w) + (s2.w + s3.w);
#pragma unroll
            for (int e = 0; e < 4; e++) {
                int j = q4 * 4 + e;
                float acc = rsum[e] + bp[j];
                int r = j / 41, w = j - r * 41;
                if (w < D_) S[OFF_SKT + g * 160 + r * 40 + w] = tanh_acc(acc);
                else        S[OFF_SSIG + g * 4 + r] = sigm(acc);
            }
        }
        __syncthreads();

        // ---- D: key norms (tid<32) + LU selection (warps 8..15) ----
        if (tid < 32) {
            int g = tid >> 2, r = tid & 3;
            const float* kk = S + OFF_SKT + g * 160 + r * 40;
            float ss = 0.f;
            for (int d = 0; d < D_; d++) ss = fmaf(kk[d], kk[d], ss);
            S[OFF_KN + tid] = __fsqrt_rn(ss) + 1e-8f;
        } else if (warp >= 8) {
            int g = warp - 8;
            const float* wu = S + OFF_WU + g * NSLOT;
            float v0 = wu[lane], v1 = wu[lane + 32], v2 = wu[lane + 64], v3 = wu[lane + 96];
            int i0 = lane, i1 = lane + 32, i2 = lane + 64, i3 = lane + 96;
#pragma unroll
            for (int s = 0; s < R_; s++) {
                float bv = v0; int bi = i0;
                if (v1 < bv || (v1 == bv && i1 < bi)) { bv = v1; bi = i1; }
                if (v2 < bv || (v2 == bv && i2 < bi)) { bv = v2; bi = i2; }
                if (v3 < bv || (v3 == bv && i3 < bi)) { bv = v3; bi = i3; }
#pragma unroll
                for (int o = 16; o > 0; o >>= 1) {
                    float ov = __shfl_xor_sync(0xffffffffu, bv, o);
                    int   oi = __shfl_xor_sync(0xffffffffu, bi, o);
                    if (ov < bv || (ov == bv && oi < bi)) { bv = ov; bi = oi; }
                }
                if (lane == 0) s_luI[g * 4 + s] = bi;
                if      (bi == i0) v0 = 3.0e38f;
                else if (bi == i1) v1 = 3.0e38f;
                else if (bi == i2) v2 = 3.0e38f;
                else if (bi == i3) v3 = 3.0e38f;
            }
        }
        __syncthreads();

        // ---- E: round keys; build skn ----
#pragma unroll
        for (int s = 0; s < 3; s++) {
            int i = tid + s * TPB;
            if (i < GB * 160) {
                int g = i / 160, j = i - g * 160;
                int r = j / 40;
                float raw = S[OFF_SKT + i];
                float nrm = S[OFF_KN + g * 4 + r];
                S[OFF_SKN + i] = tf32r(__fdiv_rn(raw, nrm));
                S[OFF_SKT + i] = tf32r(raw);
            }
        }
        __syncthreads();

        // ---- F: cosine logits (stride-41 M, conflict-free) ----
#pragma unroll
        for (int s = 0; s < 2; s++) {
            int p = tid + s * TPB;
            int g = p >> 7, n = p & 127;
            const float* Mr = S + OFF_SM + g * NSLOT * MSTR + n * MSTR;
            const float* kn = S + OFF_SKN + g * 160;
            float rinv = __fdiv_rn(1.f, S[OFF_MN + p]);
            float a0 = 0.f, a1 = 0.f, a2 = 0.f, a3 = 0.f;
            for (int d = 0; d < D_; d++) {
                float mn = tf32r(Mr[d] * rinv);
                a0 = fmaf(mn, kn[d],       a0);
                a1 = fmaf(mn, kn[40 + d],  a1);
                a2 = fmaf(mn, kn[80 + d],  a2);
                a3 = fmaf(mn, kn[120 + d], a3);
            }
            float* sw = S + OFF_SWR + g * 512;
            sw[n] = a0; sw[128 + n] = a1; sw[256 + n] = a2; sw[384 + n] = a3;
        }
        __syncthreads();

        // ---- G: softmax per (g,r) ----
        for (int row = warp; row < GB * R_; row += 16) {
            int g = row >> 2, r = row & 3;
            float* sw = S + OFF_SWR + g * 512 + r * 128;
            float v0 = sw[lane], v1 = sw[lane + 32], v2 = sw[lane + 64], v3 = sw[lane + 96];
            float mx = fmaxf(fmaxf(v0, v1), fmaxf(v2, v3));
            for (int o = 16; o > 0; o >>= 1) mx = fmaxf(mx, __shfl_xor_sync(0xffffffffu, mx, o));
            float e0 = exp_acc(v0 - mx), e1 = exp_acc(v1 - mx), e2 = exp_acc(v2 - mx), e3 = exp_acc(v3 - mx);
            float ssum = e0 + e1 + e2 + e3;
            for (int o = 16; o > 0; o >>= 1) ssum += __shfl_xor_sync(0xffffffffu, ssum, o);
            sw[lane]      = __fdiv_rn(e0, ssum);
            sw[lane + 32] = __fdiv_rn(e1, ssum);
            sw[lane + 64] = __fdiv_rn(e2, ssum);
            sw[lane + 96] = __fdiv_rn(e3, ssum);
        }
        __syncthreads();

        // ---- H: usage update + wrOld<-swr + memory write + round swr in place ----
#pragma unroll
        for (int s = 0; s < 2; s++) {
            int p = tid + s * TPB;
            int g = p >> 7, n = p & 127;
            float* wro = S + OFF_WRO + g * 512;
            float* sw  = S + OFF_SWR + g * 512;
            int lu0 = s_luI[g*4], lu1 = s_luI[g*4+1], lu2 = s_luI[g*4+2], lu3 = s_luI[g*4+3];
            float wlu = (n == lu0 || n == lu1 || n == lu2 || n == lu3) ? 1.f : 0.f;
            float sg0 = S[OFF_SSIG + g*4], sg1 = S[OFF_SSIG + g*4+1];
            float sg2 = S[OFF_SSIG + g*4+2], sg3 = S[OFF_SSIG + g*4+3];
            float wo0 = wro[n], wo1 = wro[128+n], wo2 = wro[256+n], wo3 = wro[384+n];
            float ww0 = sg0 * wo0 + (1.f - sg0) * wlu;
            float ww1 = sg1 * wo1 + (1.f - sg1) * wlu;
            float ww2 = sg2 * wo2 + (1.f - sg2) * wlu;
            float ww3 = sg3 * wo3 + (1.f - sg3) * wlu;
            float sr0 = sw[n], sr1 = sw[128+n], sr2 = sw[256+n], sr3 = sw[384+n];
            float v = 0.95f * S[OFF_WU + p];
            v += sr0 + ww0; v += sr1 + ww1; v += sr2 + ww2; v += sr3 + ww3;
            S[OFF_WU + p] = v;
            wro[n] = sr0; wro[128+n] = sr1; wro[256+n] = sr2; wro[384+n] = sr3;
            sw[n] = tf32r(sr0); sw[128+n] = tf32r(sr1); sw[256+n] = tf32r(sr2); sw[384+n] = tf32r(sr3);
            float wt0 = tf32r(ww0), wt1 = tf32r(ww1), wt2 = tf32r(ww2), wt3 = tf32r(ww3);
            float* Mr = S + OFF_SM + g * NSLOT * MSTR + n * MSTR;
            const float* kT = S + OFF_SKT + g * 160;
            bool zero_base = (n == lu3);
            for (int d = 0; d < D_; d++) {
                float base = zero_base ? 0.f : Mr[d];
                float add = 0.f;
                add = fmaf(wt0, kT[d],       add);
                add = fmaf(wt1, kT[40 + d],  add);
                add = fmaf(wt2, kT[80 + d],  add);
                add = fmaf(wt3, kT[120 + d], add);
                Mr[d] = base + add;
            }
        }
        __syncthreads();

        // ---- J: read einsum -> rhT r-part ----
#pragma unroll
        for (int s = 0; s < 3; s++) {
            int i = tid + s * TPB;
            if (i < GB * R_ * D_) {
                int g = i / 160, j = i - g * 160;
                int r = j / 40, d = j - r * 40;
                const float* sw = S + OFF_SWR + g * 512 + r * 128;
                const float* Mc = S + OFF_SM + g * NSLOT * MSTR + d;
                float a0 = 0.f, a1 = 0.f, a2 = 0.f, a3 = 0.f;
                for (int n = 0; n < NSLOT; n += 4) {
                    a0 = fmaf(sw[n],     tf32r(Mc[(n)     * MSTR]), a0);
                    a1 = fmaf(sw[n + 1], tf32r(Mc[(n + 1) * MSTR]), a1);
                    a2 = fmaf(sw[n + 2], tf32r(Mc[(n + 2) * MSTR]), a2);
                    a3 = fmaf(sw[n + 3], tf32r(Mc[(n + 3) * MSTR]), a3);
                }
                float acc = (a0 + a1) + (a2 + a3);
                S[OFF_RHT + g * 361 + j] = tf32r(acc);
            }
        }
        __syncthreads();

        // ---- K: classifier ----
        for (int o = warp; o < GB * C_; o += 16) {
            int g = o / C_, cl = o - g * C_;
            const float* rh = S + OFF_RHT + g * 361;
            float acc = 0.f;
            for (int j = lane; j < KRH; j += 32) {
                float v = (j < H_) ? rh[R_*D_ + j] : rh[j - H_];
                acc = fmaf(v, g_WcT[j * C_ + cl], acc);
            }
#pragma unroll
            for (int o2 = 16; o2 > 0; o2 >>= 1) acc += __shfl_xor_sync(0xffffffffu, acc, o2);
            if (lane == 0) S[OFF_SLOG + o] = acc + bc[cl];
        }
        __syncthreads();

        // ---- L: probs + loss/acc rows ----
        if (tid < GB) {
            int g = tid;
            int m = (bb + g) * T_ + t;
            const float* lg = S + OFF_SLOG + g * C_;
            float mx = lg[0]; int am = 0;
            for (int c = 1; c < C_; c++) if (lg[c] > mx) { mx = lg[c]; am = c; }
            float e[C_], ssum = 0.f;
            for (int c = 0; c < C_; c++) { e[c] = exp_acc(lg[c] - mx); ssum += e[c]; }
            float pr[C_];
            for (int c = 0; c < C_; c++) { pr[c] = __fdiv_rn(e[c], ssum); out[m * C_ + c] = pr[c]; }
            float mp = pr[0];
            for (int c = 1; c < C_; c++) mp = fmaxf(mp, pr[c]);
            float se = 0.f;
            for (int c = 0; c < C_; c++) se += exp_acc(pr[c] - mp);
            int lab = labels[m];
            g_rowloss[m] = (float)(log((double)se)) + mp - pr[lab];
            g_rowcorr[m] = (am == lab) ? 1.f : 0.f;
        }
        __syncthreads();
    }
}

// ---------------- deterministic final reduction ----------------
__global__ __launch_bounds__(1024) void finalize_kernel(float* __restrict__ out) {
    __shared__ float sl[1024], sa[1024];
    int tid = threadIdx.x;
    float l = 0.f, a = 0.f;
    for (int i = tid; i < BT; i += 1024) { l += g_rowloss[i]; a += g_rowcorr[i]; }
    sl[tid] = l; sa[tid] = a;
    __syncthreads();
    for (int s = 512; s > 0; s >>= 1) {
        if (tid < s) { sl[tid] += sl[tid + s]; sa[tid] += sa[tid + s]; }
        __syncthreads();
    }
    if (tid == 0) {
        out[BT * C_]     = __fdiv_rn(sl[0], (float)BT);
        out[BT * C_ + 1] = __fdiv_rn(sa[0], (float)BT);
    }
}

// ---------------- launch ----------------
extern "C" void kernel_launch(void* const* d_in, const int* in_sizes, int n_in,
                              void* d_out, int out_size) {
    const float* images = (const float*)d_in[0];
    const int*   labels = (const int*)d_in[1];
    const float* Wx     = (const float*)d_in[2];
    const float* Wh     = (const float*)d_in[3];
    const float* b_lstm = (const float*)d_in[4];
    const float* Wp     = (const float*)d_in[5];
    const float* bp     = (const float*)d_in[6];
    const float* Wc     = (const float*)d_in[7];
    const float* bc     = (const float*)d_in[8];
    float* out = (float*)d_out;

    float* pXpre;
    cudaGetSymbolAddress((void**)&pXpre, g_Xpre);

    cudaFuncSetAttribute(fused_kernel, cudaFuncAttributeMaxDynamicSharedMemorySize, SMEM_BYTES);

    init_kernel<<<320, 256>>>(Wx, Wh, Wp, Wc);

    {
        dim3 grid(13, BT / 128);
        gemm0_kernel<<<grid, 256>>>(images, Wx, b_lstm, labels, pXpre);
    }

    fused_kernel<<<NBLK, TPB, SMEM_BYTES>>>(bp, bc, labels, out);

    finalize_kernel<<<1, 1024>>>(out);
}